// round 15
// baseline (speedup 1.0000x reference)
#include <cuda_runtime.h>
#include <math.h>

#define NN 50000
#define EE 800000
#define FULLM 0xFFFFFFFFu

typedef unsigned long long u64;

// ---------------- scratch ----------------
__device__ float g_h1[NN * 128];
__device__ float g_h2[NN];
__device__ float g_h3[NN * 32];
__device__ float g_out2[NN];
__device__ float g_out3[NN * 32];
__device__ float g_score1[EE];
__device__ float g_s2a[EE];
__device__ float g_s3a[EE];
__device__ int g_deg[NN];
__device__ int g_rowptr[NN + 1];
__device__ int g_cursor[NN];
__device__ int g_perm[EE];
__device__ int g_srcs[EE];
__device__ int g_dsts[EE];
__device__ int g_bsum[256];
__device__ int g_boff[256];
__device__ unsigned long long g_packed;
__device__ unsigned int g_lmax_ord;
__device__ unsigned int g_key1[2];
__device__ unsigned int g_key2[2];

// ---------------- helpers ----------------
__device__ __forceinline__ float lrelu(float x) { return x >= 0.f ? x : 0.2f * x; }

__device__ __forceinline__ u64 f2pack(float lo, float hi) {
    u64 r; asm("mov.b64 %0, {%1, %2};" : "=l"(r) : "f"(lo), "f"(hi)); return r;
}
__device__ __forceinline__ void f2unpack(u64 v, float &lo, float &hi) {
    asm("mov.b64 {%0, %1}, %2;" : "=f"(lo), "=f"(hi) : "l"(v));
}
__device__ __forceinline__ u64 ffma2(u64 a, u64 b, u64 c) {
    u64 d; asm("fma.rn.f32x2 %0, %1, %2, %3;" : "=l"(d) : "l"(a), "l"(b), "l"(c)); return d;
}
__device__ __forceinline__ float f2sum(u64 v) {
    float lo, hi; f2unpack(v, lo, hi); return lo + hi;
}

__device__ __forceinline__ unsigned ordf(float x) {
    unsigned u = __float_as_uint(x);
    return (u & 0x80000000u) ? ~u : (u | 0x80000000u);
}
__device__ __forceinline__ float ordinv(unsigned o) {
    return (o & 0x80000000u) ? __uint_as_float(o & 0x7FFFFFFFu) : __uint_as_float(~o);
}

__device__ __forceinline__ unsigned rotl32(unsigned v, int r) { return (v << r) | (v >> (32 - r)); }

__device__ __forceinline__ void threefry2x32(unsigned k0, unsigned k1, unsigned c0, unsigned c1,
                                             unsigned &o0, unsigned &o1) {
    unsigned ks2 = k0 ^ k1 ^ 0x1BD11BDAu;
    unsigned x0 = c0 + k0, x1 = c1 + k1;
#define TFR(r) { x0 += x1; x1 = rotl32(x1, r); x1 ^= x0; }
    TFR(13) TFR(15) TFR(26) TFR(6)  x0 += k1;  x1 += ks2 + 1u;
    TFR(17) TFR(29) TFR(16) TFR(24) x0 += ks2; x1 += k0 + 2u;
    TFR(13) TFR(15) TFR(26) TFR(6)  x0 += k0;  x1 += k1 + 3u;
    TFR(17) TFR(29) TFR(16) TFR(24) x0 += k1;  x1 += ks2 + 4u;
    TFR(13) TFR(15) TFR(26) TFR(6)  x0 += ks2; x1 += k0 + 5u;
#undef TFR
    o0 = x0; o1 = x1;
}

__device__ __forceinline__ unsigned jax_bits32(unsigned k0, unsigned k1, unsigned i) {
    unsigned o0, o1;
    threefry2x32(k0, k1, 0u, i, o0, o1);
    return o0 ^ o1;
}

__device__ __forceinline__ float gumbel_bits(unsigned bits) {
    float f = __uint_as_float((bits >> 9) | 0x3f800000u) - 1.0f;
    const float TINY = 1.1754943508222875e-38f;
    f = fmaxf(f, TINY);
    return -logf(-logf(f));
}

// ---------------- CSR build ----------------
__global__ void hist_kernel(const int* __restrict__ ei, int E) {
    int e = blockIdx.x * blockDim.x + threadIdx.x;
    if (e < E) atomicAdd(&g_deg[ei[E + e]], 1);
}

__global__ void scanA_kernel(int N) {
    __shared__ int sm[256];
    int t = threadIdx.x, i = blockIdx.x * 256 + t;
    int v = (i < N) ? g_deg[i] : 0;
    sm[t] = v;
    __syncthreads();
    for (int off = 1; off < 256; off <<= 1) {
        int x = (t >= off) ? sm[t - off] : 0;
        __syncthreads();
        sm[t] += x;
        __syncthreads();
    }
    if (i < N) {
        g_rowptr[i] = sm[t] - v;
        g_deg[i] = 0;
    }
    if (t == 255) g_bsum[blockIdx.x] = sm[255];
}

__global__ void scanB_kernel(int NB, int N) {
    __shared__ int sm[256];
    int t = threadIdx.x;
    int v = (t < NB) ? g_bsum[t] : 0;
    sm[t] = v;
    __syncthreads();
    for (int off = 1; off < 256; off <<= 1) {
        int x = (t >= off) ? sm[t - off] : 0;
        __syncthreads();
        sm[t] += x;
        __syncthreads();
    }
    if (t < NB) g_boff[t] = sm[t] - v;
    if (t == 255) g_rowptr[N] = sm[255];
    if (t == 0) {
        g_packed = 0ull;
        g_lmax_ord = 0u;
        unsigned a0, a1, b0, b1;
        threefry2x32(0u, 42u, 0u, 0u, a0, a1);
        threefry2x32(0u, 42u, 0u, 1u, b0, b1);
        g_key1[0] = a0; g_key1[1] = a1;
        g_key2[0] = b0; g_key2[1] = b1;
    }
}

__global__ void scanC_kernel(int N) {
    int i = blockIdx.x * 256 + threadIdx.x;
    if (i < N) {
        int r = g_rowptr[i] + g_boff[blockIdx.x];
        g_rowptr[i] = r;
        g_cursor[i] = r;
    }
}

__global__ void scatter_kernel(const int* __restrict__ ei, int E) {
    int e = blockIdx.x * blockDim.x + threadIdx.x;
    if (e < E) {
        int s = ei[e];
        int d = ei[E + e];
        int pos = atomicAdd(&g_cursor[d], 1);
        g_perm[pos] = e;
        g_srcs[pos] = s;
        g_dsts[pos] = d;
    }
}

// ---------------- gemm1: h1 = X @ Wl1 + bl1 ----------------
__global__ void gemm1_kernel(const float* __restrict__ X, const float* __restrict__ W,
                             const float* __restrict__ b, int N) {
    extern __shared__ float sm[];
    float* sW = sm;            // 16384
    float* sB = sm + 16384;    // 128
    float* sX = sm + 16512;    // 4096
    int tid = threadIdx.x;
    for (int i = tid; i < 4096; i += blockDim.x)
        reinterpret_cast<float4*>(sW)[i] = reinterpret_cast<const float4*>(W)[i];
    if (tid < 32) reinterpret_cast<float4*>(sB)[tid] = reinterpret_cast<const float4*>(b)[tid];
    __syncthreads();
    int w = tid >> 5, lane = tid & 31;
    int ntiles = (N + 31) / 32;
    for (int tile = blockIdx.x; tile < ntiles; tile += gridDim.x) {
        int row0 = tile * 32;
        for (int i = tid; i < 1024; i += blockDim.x) {
            int rr = i >> 5, c = i & 31;
            int row = row0 + rr;
            float4 v = make_float4(0.f, 0.f, 0.f, 0.f);
            if (row < N) v = reinterpret_cast<const float4*>(X + (size_t)row * 128)[c];
            reinterpret_cast<float4*>(sX)[i] = v;
        }
        __syncthreads();
        float4 a0 = make_float4(0,0,0,0), a1 = a0, a2 = a0, a3 = a0;
#pragma unroll 4
        for (int d = 0; d < 128; d++) {
            float4 wv = reinterpret_cast<float4*>(sW)[d * 32 + lane];
            float x0 = sX[w * 128 + d];
            float x1 = sX[(w + 8) * 128 + d];
            float x2 = sX[(w + 16) * 128 + d];
            float x3 = sX[(w + 24) * 128 + d];
            a0.x = fmaf(x0, wv.x, a0.x); a0.y = fmaf(x0, wv.y, a0.y); a0.z = fmaf(x0, wv.z, a0.z); a0.w = fmaf(x0, wv.w, a0.w);
            a1.x = fmaf(x1, wv.x, a1.x); a1.y = fmaf(x1, wv.y, a1.y); a1.z = fmaf(x1, wv.z, a1.z); a1.w = fmaf(x1, wv.w, a1.w);
            a2.x = fmaf(x2, wv.x, a2.x); a2.y = fmaf(x2, wv.y, a2.y); a2.z = fmaf(x2, wv.z, a2.z); a2.w = fmaf(x2, wv.w, a2.w);
            a3.x = fmaf(x3, wv.x, a3.x); a3.y = fmaf(x3, wv.y, a3.y); a3.z = fmaf(x3, wv.z, a3.z); a3.w = fmaf(x3, wv.w, a3.w);
        }
        float4 b4 = reinterpret_cast<float4*>(sB)[lane];
        float4 accs[4] = {a0, a1, a2, a3};
#pragma unroll
        for (int j = 0; j < 4; j++) {
            int row = row0 + w + 8 * j;
            if (row < N) {
                float4 o = make_float4(accs[j].x + b4.x, accs[j].y + b4.y,
                                       accs[j].z + b4.z, accs[j].w + b4.w);
                reinterpret_cast<float4*>(g_h1 + (size_t)row * 128)[lane] = o;
            }
        }
        __syncthreads();
    }
}

// ---------------- layer-1 edge scores: FFMA2 + interleaved transposed We ----------------
// sW2[((dc*4+cm)*32+lane)*4+j] = We[(dc*4+j)][4*lane+cm] ; conflict-free LDS.128
__global__ void score1_kernel(const float* __restrict__ ea, const float* __restrict__ We,
                              const float* __restrict__ att, int E) {
    __shared__ float sW2[2048];
    __shared__ float4 sAtt[32];
    int tid = threadIdx.x;
    for (int i = tid; i < 2048; i += blockDim.x) {
        int j = i & 3, ln = (i >> 2) & 31, cm = (i >> 7) & 3, dc = i >> 9;
        sW2[i] = We[(dc * 4 + j) * 128 + 4 * ln + cm];
    }
    if (tid < 32) sAtt[tid] = reinterpret_cast<const float4*>(att)[tid];
    __syncthreads();
    int lane = tid & 31;
    int wid = (blockIdx.x * blockDim.x + tid) >> 5;
    int NW = (gridDim.x * blockDim.x) >> 5;
    float4 at = sAtt[lane];
    for (int pos = wid * 2; pos < E; pos += NW * 2) {
        bool ok1 = (pos + 1 < E);
        int pb = ok1 ? pos + 1 : pos;
        int s0 = g_srcs[pos], d0 = g_dsts[pos], e0 = g_perm[pos];
        int s1 = g_srcs[pb],  d1 = g_dsts[pb],  e1 = g_perm[pb];
        float4 hj0 = reinterpret_cast<const float4*>(g_h1 + (size_t)s0 * 128)[lane];
        float4 hi0 = reinterpret_cast<const float4*>(g_h1 + (size_t)d0 * 128)[lane];
        float4 hj1 = reinterpret_cast<const float4*>(g_h1 + (size_t)s1 * 128)[lane];
        float4 hi1 = reinterpret_cast<const float4*>(g_h1 + (size_t)d1 * 128)[lane];
        const float4* eaA = reinterpret_cast<const float4*>(ea + (size_t)e0 * 16);
        const float4* eaB = reinterpret_cast<const float4*>(ea + (size_t)e1 * 16);
        u64 ep0[8], ep1[8];
#pragma unroll
        for (int j = 0; j < 4; j++) {
            float4 t0 = __ldg(eaA + j);
            float4 t1 = __ldg(eaB + j);
            ep0[2*j]   = f2pack(t0.x, t0.y);
            ep0[2*j+1] = f2pack(t0.z, t0.w);
            ep1[2*j]   = f2pack(t1.x, t1.y);
            ep1[2*j+1] = f2pack(t1.z, t1.w);
        }
        u64 acc0[4] = {0ull, 0ull, 0ull, 0ull};
        u64 acc1[4] = {0ull, 0ull, 0ull, 0ull};
#pragma unroll
        for (int dc = 0; dc < 4; dc++) {
#pragma unroll
            for (int cm = 0; cm < 4; cm++) {
                float4 wv = *reinterpret_cast<float4*>(&sW2[((dc * 4 + cm) * 32 + lane) * 4]);
                u64 wp0 = f2pack(wv.x, wv.y);
                u64 wp1 = f2pack(wv.z, wv.w);
                acc0[cm] = ffma2(ep0[2*dc],     wp0, acc0[cm]);
                acc0[cm] = ffma2(ep0[2*dc + 1], wp1, acc0[cm]);
                acc1[cm] = ffma2(ep1[2*dc],     wp0, acc1[cm]);
                acc1[cm] = ffma2(ep1[2*dc + 1], wp1, acc1[cm]);
            }
        }
        float c0x = f2sum(acc0[0]), c0y = f2sum(acc0[1]), c0z = f2sum(acc0[2]), c0w = f2sum(acc0[3]);
        float c1x = f2sum(acc1[0]), c1y = f2sum(acc1[1]), c1z = f2sum(acc1[2]), c1w = f2sum(acc1[3]);
        float p0 = at.x * lrelu(hi0.x + hj0.x + c0x)
                 + at.y * lrelu(hi0.y + hj0.y + c0y)
                 + at.z * lrelu(hi0.z + hj0.z + c0z)
                 + at.w * lrelu(hi0.w + hj0.w + c0w);
        float p1 = at.x * lrelu(hi1.x + hj1.x + c1x)
                 + at.y * lrelu(hi1.y + hj1.y + c1y)
                 + at.z * lrelu(hi1.z + hj1.z + c1z)
                 + at.w * lrelu(hi1.w + hj1.w + c1w);
#pragma unroll
        for (int o = 16; o; o >>= 1) {
            p0 += __shfl_xor_sync(FULLM, p0, o);
            p1 += __shfl_xor_sync(FULLM, p1, o);
        }
        if (lane == 0) {
            g_score1[pos] = p0;
            if (ok1) g_score1[pos + 1] = p1;
        }
    }
}

// ---------------- fused layer-1 softmax/aggregate + gemm23 (FFMA2 tail) ----------------
// sG3[(dc*32+lane)*4+j] = Wl3[(dc*4+j)][lane], dc 0..31 ; sG2[i] = Wl2[i]
__global__ void agg1_gemm_kernel(const float* __restrict__ bias1,
                                 const float* __restrict__ Wl2, const float* __restrict__ bl2,
                                 const float* __restrict__ Wl3, const float* __restrict__ bl3, int N) {
    __shared__ float sG3[4096];
    __shared__ float sG2[128];
    __shared__ float4 sB1[32];
    int tid = threadIdx.x;
    for (int i = tid; i < 4096; i += blockDim.x) {
        int j = i & 3, ln = (i >> 2) & 31, dc = i >> 7;
        sG3[i] = Wl3[(dc * 4 + j) * 32 + ln];
    }
    if (tid < 128) sG2[tid] = Wl2[tid];
    if (tid < 32) sB1[tid] = reinterpret_cast<const float4*>(bias1)[tid];
    __syncthreads();
    int lane = tid & 31;
    int wid = (blockIdx.x * blockDim.x + tid) >> 5;
    int nw = (gridDim.x * blockDim.x) >> 5;
    float b2 = __ldg(bl2);
    float b3 = __ldg(bl3 + lane);
    for (int i = wid; i < N; i += nw) {
        int beg = g_rowptr[i], end = g_rowptr[i + 1];
        int deg = end - beg;
        int p0 = beg + lane, p1 = beg + 32 + lane;
        bool a0 = p0 < end, a1 = p1 < end;
        float s0 = a0 ? g_score1[p0] : -INFINITY;
        float s1 = a1 ? g_score1[p1] : -INFINITY;
        int i0 = a0 ? g_srcs[p0] : 0;
        int i1 = a1 ? g_srcs[p1] : 0;
        float m = fmaxf(s0, s1);
        for (int p = beg + 64 + lane; p < end; p += 32) m = fmaxf(m, g_score1[p]);
#pragma unroll
        for (int o = 16; o; o >>= 1) m = fmaxf(m, __shfl_xor_sync(FULLM, m, o));
        float e0 = a0 ? expf(s0 - m) : 0.f;
        float e1 = a1 ? expf(s1 - m) : 0.f;
        float den = e0 + e1;
        for (int p = beg + 64 + lane; p < end; p += 32) den += expf(g_score1[p] - m);
#pragma unroll
        for (int o = 16; o; o >>= 1) den += __shfl_xor_sync(FULLM, den, o);
        float inv = 1.0f / (den + 1e-16f);
        float4 acc = make_float4(0.f, 0.f, 0.f, 0.f);
        int dmain = deg < 64 ? deg : 64;
        int k = 0;
        for (; k + 8 <= dmain; k += 8) {
            int   ss[8]; float ww[8];
#pragma unroll
            for (int j = 0; j < 8; j++) {
                ss[j] = __shfl_sync(FULLM, (k + j < 32) ? i0 : i1, (k + j) & 31);
                ww[j] = __shfl_sync(FULLM, (k + j < 32) ? e0 : e1, (k + j) & 31);
            }
            float4 vv[8];
#pragma unroll
            for (int j = 0; j < 8; j++)
                vv[j] = reinterpret_cast<const float4*>(g_h1 + (size_t)ss[j] * 128)[lane];
#pragma unroll
            for (int j = 0; j < 8; j++) {
                float aw = ww[j] * inv;
                acc.x = fmaf(aw, vv[j].x, acc.x);
                acc.y = fmaf(aw, vv[j].y, acc.y);
                acc.z = fmaf(aw, vv[j].z, acc.z);
                acc.w = fmaf(aw, vv[j].w, acc.w);
            }
        }
        for (; k + 4 <= dmain; k += 4) {
            int   ss[4]; float ww[4];
#pragma unroll
            for (int j = 0; j < 4; j++) {
                ss[j] = __shfl_sync(FULLM, (k + j < 32) ? i0 : i1, (k + j) & 31);
                ww[j] = __shfl_sync(FULLM, (k + j < 32) ? e0 : e1, (k + j) & 31);
            }
            float4 vv[4];
#pragma unroll
            for (int j = 0; j < 4; j++)
                vv[j] = reinterpret_cast<const float4*>(g_h1 + (size_t)ss[j] * 128)[lane];
#pragma unroll
            for (int j = 0; j < 4; j++) {
                float aw = ww[j] * inv;
                acc.x = fmaf(aw, vv[j].x, acc.x);
                acc.y = fmaf(aw, vv[j].y, acc.y);
                acc.z = fmaf(aw, vv[j].z, acc.z);
                acc.w = fmaf(aw, vv[j].w, acc.w);
            }
        }
        for (; k < dmain; k++) {
            int src  = __shfl_sync(FULLM, (k < 32) ? i0 : i1, k & 31);
            float ee = __shfl_sync(FULLM, (k < 32) ? e0 : e1, k & 31);
            float aw = ee * inv;
            float4 v = reinterpret_cast<const float4*>(g_h1 + (size_t)src * 128)[lane];
            acc.x = fmaf(aw, v.x, acc.x);
            acc.y = fmaf(aw, v.y, acc.y);
            acc.z = fmaf(aw, v.z, acc.z);
            acc.w = fmaf(aw, v.w, acc.w);
        }
        for (int p = beg + 64; p < end; p++) {
            float aw = expf(g_score1[p] - m) * inv;
            float4 v = reinterpret_cast<const float4*>(g_h1 + (size_t)g_srcs[p] * 128)[lane];
            acc.x = fmaf(aw, v.x, acc.x);
            acc.y = fmaf(aw, v.y, acc.y);
            acc.z = fmaf(aw, v.z, acc.z);
            acc.w = fmaf(aw, v.w, acc.w);
        }
        float4 bb = sB1[lane];
        float4 lr = make_float4(acc.x + bb.x, acc.y + bb.y, acc.z + bb.z, acc.w + bb.w);
        // gemm23 tail via FFMA2: d = 4*dc + {0,1,2,3} → comps x,y,z,w from src lane dc
        u64 a3p = 0ull, a2p = 0ull;
#pragma unroll 8
        for (int dc = 0; dc < 32; dc++) {
            float vx = __shfl_sync(FULLM, lr.x, dc);
            float vy = __shfl_sync(FULLM, lr.y, dc);
            float vz = __shfl_sync(FULLM, lr.z, dc);
            float vw = __shfl_sync(FULLM, lr.w, dc);
            u64 vp0 = f2pack(vx, vy);
            u64 vp1 = f2pack(vz, vw);
            float4 w3 = *reinterpret_cast<float4*>(&sG3[(dc * 32 + lane) * 4]);
            float4 w2 = *reinterpret_cast<float4*>(&sG2[dc * 4]);
            a3p = ffma2(vp0, f2pack(w3.x, w3.y), a3p);
            a3p = ffma2(vp1, f2pack(w3.z, w3.w), a3p);
            a2p = ffma2(vp0, f2pack(w2.x, w2.y), a2p);
            a2p = ffma2(vp1, f2pack(w2.z, w2.w), a2p);
        }
        g_h3[(size_t)i * 32 + lane] = f2sum(a3p) + b3;
        if (lane == 0) g_h2[i] = f2sum(a2p) + b2;
    }
}

// ---------------- fused layer-2+3 edge scores: FFMA2 + interleaved transposed weights ----------------
// sw3v[(dc*32+lane)*4+j] = We3[(dc*4+j)][lane] ; sw2v[dc*4+j] = We2[dc*4+j]
__global__ void score23_kernel(const float* __restrict__ ea,
                               const float* __restrict__ We2, const float* __restrict__ att2,
                               const float* __restrict__ We3, const float* __restrict__ att3, int E) {
    __shared__ float sw3v[512];
    __shared__ float sw2v[16];
    __shared__ float sA3[32];
    int tid = threadIdx.x;
    for (int i = tid; i < 512; i += blockDim.x) {
        int j = i & 3, ln = (i >> 2) & 31, dc = i >> 7;
        sw3v[i] = We3[(dc * 4 + j) * 32 + ln];
    }
    if (tid < 16) sw2v[tid] = We2[tid];
    if (tid < 32) sA3[tid] = att3[tid];
    __syncthreads();
    int lane = tid & 31;
    int wid = (blockIdx.x * blockDim.x + tid) >> 5;
    int NW = (gridDim.x * blockDim.x) >> 5;
    float a2 = __ldg(att2);
    float at3 = sA3[lane];
    for (int pos = wid * 2; pos < E; pos += NW * 2) {
        bool ok1 = (pos + 1 < E);
        int pb = ok1 ? pos + 1 : pos;
        int s0 = g_srcs[pos], d0 = g_dsts[pos], e0 = g_perm[pos];
        int s1 = g_srcs[pb],  d1 = g_dsts[pb],  e1 = g_perm[pb];
        float h2j0 = __ldg(&g_h2[s0]), h2i0 = __ldg(&g_h2[d0]);
        float h2j1 = __ldg(&g_h2[s1]), h2i1 = __ldg(&g_h2[d1]);
        float h3j0 = g_h3[(size_t)s0 * 32 + lane];
        float h3i0 = g_h3[(size_t)d0 * 32 + lane];
        float h3j1 = g_h3[(size_t)s1 * 32 + lane];
        float h3i1 = g_h3[(size_t)d1 * 32 + lane];
        const float4* eaA = reinterpret_cast<const float4*>(ea + (size_t)e0 * 16);
        const float4* eaB = reinterpret_cast<const float4*>(ea + (size_t)e1 * 16);
        u64 ep0[8], ep1[8];
#pragma unroll
        for (int j = 0; j < 4; j++) {
            float4 t0 = __ldg(eaA + j);
            float4 t1 = __ldg(eaB + j);
            ep0[2*j]   = f2pack(t0.x, t0.y);
            ep0[2*j+1] = f2pack(t0.z, t0.w);
            ep1[2*j]   = f2pack(t1.x, t1.y);
            ep1[2*j+1] = f2pack(t1.z, t1.w);
        }
        u64 e3p0 = 0ull, e3p1 = 0ull, e2p0 = 0ull, e2p1 = 0ull;
#pragma unroll
        for (int dc = 0; dc < 4; dc++) {
            float4 w3 = *reinterpret_cast<float4*>(&sw3v[(dc * 32 + lane) * 4]);
            float4 w2 = *reinterpret_cast<float4*>(&sw2v[dc * 4]);
            u64 w3a = f2pack(w3.x, w3.y), w3b = f2pack(w3.z, w3.w);
            u64 w2a = f2pack(w2.x, w2.y), w2b = f2pack(w2.z, w2.w);
            e3p0 = ffma2(ep0[2*dc], w3a, e3p0); e3p0 = ffma2(ep0[2*dc+1], w3b, e3p0);
            e3p1 = ffma2(ep1[2*dc], w3a, e3p1); e3p1 = ffma2(ep1[2*dc+1], w3b, e3p1);
            e2p0 = ffma2(ep0[2*dc], w2a, e2p0); e2p0 = ffma2(ep0[2*dc+1], w2b, e2p0);
            e2p1 = ffma2(ep1[2*dc], w2a, e2p1); e2p1 = ffma2(ep1[2*dc+1], w2b, e2p1);
        }
        float e30 = f2sum(e3p0), e31 = f2sum(e3p1);
        float e20 = f2sum(e2p0), e21 = f2sum(e2p1);
        float p30 = at3 * lrelu(h3i0 + h3j0 + e30);
        float p31 = at3 * lrelu(h3i1 + h3j1 + e31);
#pragma unroll
        for (int o = 16; o; o >>= 1) {
            p30 += __shfl_xor_sync(FULLM, p30, o);
            p31 += __shfl_xor_sync(FULLM, p31, o);
        }
        float q0 = a2 * lrelu(h2i0 + h2j0 + e20);
        float q1 = a2 * lrelu(h2i1 + h2j1 + e21);
        if (lane == 0) {
            g_s2a[pos] = q0;
            g_s3a[pos] = p30;
            if (ok1) { g_s2a[pos + 1] = q1; g_s3a[pos + 1] = p31; }
        }
    }
}

// ---------------- fused layer-2+3 softmax/aggregate + node gumbel sampling ----------------
__global__ void agg23_kernel(const float* __restrict__ bias2, const float* __restrict__ bias3, int N) {
    __shared__ unsigned long long sPk[8];
    __shared__ unsigned sLo[8];
    int tid = threadIdx.x;
    int lane = tid & 31;
    int warp = tid >> 5;
    int wid = (blockIdx.x * blockDim.x + tid) >> 5;
    int nw = (gridDim.x * blockDim.x) >> 5;
    float b2 = __ldg(bias2);
    float b3 = __ldg(bias3 + lane);
    unsigned gk0 = g_key1[0], gk1 = g_key1[1];
    unsigned long long bestPk = 0ull;
    unsigned bestLo = 0u;
    for (int i = wid; i < N; i += nw) {
        int beg = g_rowptr[i], end = g_rowptr[i + 1];
        int deg = end - beg;
        int p0 = beg + lane, p1 = beg + 32 + lane;
        bool a0 = p0 < end, a1 = p1 < end;
        float s20 = a0 ? g_s2a[p0] : -INFINITY;
        float s30 = a0 ? g_s3a[p0] : -INFINITY;
        float s21 = a1 ? g_s2a[p1] : -INFINITY;
        float s31 = a1 ? g_s3a[p1] : -INFINITY;
        int i0 = a0 ? g_srcs[p0] : 0;
        int i1 = a1 ? g_srcs[p1] : 0;
        float m2 = fmaxf(s20, s21), m3 = fmaxf(s30, s31);
        for (int p = beg + 64 + lane; p < end; p += 32) {
            m2 = fmaxf(m2, g_s2a[p]);
            m3 = fmaxf(m3, g_s3a[p]);
        }
#pragma unroll
        for (int o = 16; o; o >>= 1) {
            m2 = fmaxf(m2, __shfl_xor_sync(FULLM, m2, o));
            m3 = fmaxf(m3, __shfl_xor_sync(FULLM, m3, o));
        }
        float e20 = a0 ? expf(s20 - m2) : 0.f;
        float e21 = a1 ? expf(s21 - m2) : 0.f;
        float e30 = a0 ? expf(s30 - m3) : 0.f;
        float e31 = a1 ? expf(s31 - m3) : 0.f;
        float den2 = e20 + e21;
        float den3 = e30 + e31;
        float num2 = e20 * (a0 ? __ldg(&g_h2[i0]) : 0.f)
                   + e21 * (a1 ? __ldg(&g_h2[i1]) : 0.f);
        for (int p = beg + 64 + lane; p < end; p += 32) {
            float e2 = expf(g_s2a[p] - m2);
            den2 += e2;
            num2 += e2 * __ldg(&g_h2[g_srcs[p]]);
            den3 += expf(g_s3a[p] - m3);
        }
#pragma unroll
        for (int o = 16; o; o >>= 1) {
            den2 += __shfl_xor_sync(FULLM, den2, o);
            num2 += __shfl_xor_sync(FULLM, num2, o);
            den3 += __shfl_xor_sync(FULLM, den3, o);
        }
        float inv3 = 1.0f / (den3 + 1e-16f);
        float acc = 0.f;
        int dmain = deg < 64 ? deg : 64;
        int k = 0;
        for (; k + 8 <= dmain; k += 8) {
            int ss[8]; float ww[8];
#pragma unroll
            for (int j = 0; j < 8; j++) {
                ss[j] = __shfl_sync(FULLM, (k + j < 32) ? i0 : i1, (k + j) & 31);
                ww[j] = __shfl_sync(FULLM, (k + j < 32) ? e30 : e31, (k + j) & 31);
            }
            float vv[8];
#pragma unroll
            for (int j = 0; j < 8; j++)
                vv[j] = g_h3[(size_t)ss[j] * 32 + lane];
#pragma unroll
            for (int j = 0; j < 8; j++)
                acc = fmaf(ww[j] * inv3, vv[j], acc);
        }
        for (; k + 4 <= dmain; k += 4) {
            int ss[4]; float ww[4];
#pragma unroll
            for (int j = 0; j < 4; j++) {
                ss[j] = __shfl_sync(FULLM, (k + j < 32) ? i0 : i1, (k + j) & 31);
                ww[j] = __shfl_sync(FULLM, (k + j < 32) ? e30 : e31, (k + j) & 31);
            }
            float vv[4];
#pragma unroll
            for (int j = 0; j < 4; j++)
                vv[j] = g_h3[(size_t)ss[j] * 32 + lane];
#pragma unroll
            for (int j = 0; j < 4; j++)
                acc = fmaf(ww[j] * inv3, vv[j], acc);
        }
        for (; k < dmain; k++) {
            int src  = __shfl_sync(FULLM, (k < 32) ? i0 : i1, k & 31);
            float ee = __shfl_sync(FULLM, (k < 32) ? e30 : e31, k & 31);
            acc = fmaf(ee * inv3, g_h3[(size_t)src * 32 + lane], acc);
        }
        for (int p = beg + 64; p < end; p++) {
            float aw = expf(g_s3a[p] - m3) * inv3;
            acc = fmaf(aw, g_h3[(size_t)g_srcs[p] * 32 + lane], acc);
        }
        g_out3[(size_t)i * 32 + lane] = acc + b3;
        if (lane == 0) {
            float lg = num2 / (den2 + 1e-16f) + b2;
            g_out2[i] = lg;
            unsigned bits = jax_bits32(gk0, gk1, (unsigned)i);
            float z = lg + gumbel_bits(bits);
            unsigned long long pk = ((unsigned long long)ordf(z) << 32)
                                  | (unsigned long long)(0xFFFFFFFFu - (unsigned)i);
            if (pk > bestPk) bestPk = pk;
            unsigned lo = ordf(lg);
            if (lo > bestLo) bestLo = lo;
        }
    }
    if (lane == 0) { sPk[warp] = bestPk; sLo[warp] = bestLo; }
    __syncthreads();
    if (tid == 0) {
        unsigned long long bp = sPk[0];
        unsigned bl = sLo[0];
#pragma unroll
        for (int j = 1; j < 8; j++) {
            if (sPk[j] > bp) bp = sPk[j];
            if (sLo[j] > bl) bl = sLo[j];
        }
        atomicMax(&g_packed, bp);
        atomicMax(&g_lmax_ord, bl);
    }
}

// ---------------- finalize: sumexp + node_lp + action sampling ----------------
__global__ void finalize_kernel(float* __restrict__ out, int N) {
    __shared__ float ssum[32];
    int tid = threadIdx.x;
    int lane = tid & 31;
    int warp = tid >> 5;
    float lmax = ordinv(g_lmax_ord);
    float s = 0.f;
    for (int i = tid; i < N; i += 1024) s += expf(g_out2[i] - lmax);
#pragma unroll
    for (int o = 16; o; o >>= 1) s += __shfl_xor_sync(FULLM, s, o);
    if (lane == 0) ssum[warp] = s;
    __syncthreads();
    if (tid < 32) {
        float v = ssum[tid];
#pragma unroll
        for (int o = 16; o; o >>= 1) v += __shfl_xor_sync(FULLM, v, o);
        if (tid == 0) ssum[0] = v;
    }
    __syncthreads();
    float S = ssum[0];
    if (tid < 32) {
        unsigned long long pk = g_packed;
        unsigned sel = 0xFFFFFFFFu - (unsigned)(pk & 0xFFFFFFFFull);
        float node_lp = g_out2[sel] - lmax - logf(S);

        float logit = g_out3[(size_t)sel * 32 + lane];
        unsigned bits = jax_bits32(g_key2[0], g_key2[1], (unsigned)lane);
        float z = logit + gumbel_bits(bits);

        float bz = z;
        int bi = lane;
#pragma unroll
        for (int o = 16; o; o >>= 1) {
            float oz = __shfl_xor_sync(FULLM, bz, o);
            int oi = __shfl_xor_sync(FULLM, bi, o);
            if (oz > bz || (oz == bz && oi < bi)) { bz = oz; bi = oi; }
        }
        float m = logit;
#pragma unroll
        for (int o = 16; o; o >>= 1) m = fmaxf(m, __shfl_xor_sync(FULLM, m, o));
        float se = expf(logit - m);
#pragma unroll
        for (int o = 16; o; o >>= 1) se += __shfl_xor_sync(FULLM, se, o);
        float sel_logit = __shfl_sync(FULLM, logit, bi);
        float action_lp = sel_logit - m - logf(se);
        if (lane == 0) {
            out[0] = (float)sel;
            out[1] = (float)bi;
            out[2] = node_lp + action_lp;
        }
    }
}

// ---------------- launch ----------------
extern "C" void kernel_launch(void* const* d_in, const int* in_sizes, int n_in,
                              void* d_out, int out_size) {
    const float* x     = (const float*)d_in[0];
    const int*   ei    = (const int*)d_in[1];
    const float* ea    = (const float*)d_in[2];
    const float* Wl1   = (const float*)d_in[3];
    const float* bl1   = (const float*)d_in[4];
    const float* We1   = (const float*)d_in[5];
    const float* att1  = (const float*)d_in[6];
    const float* bias1 = (const float*)d_in[7];
    const float* Wl2   = (const float*)d_in[8];
    const float* bl2   = (const float*)d_in[9];
    const float* We2   = (const float*)d_in[10];
    const float* att2  = (const float*)d_in[11];
    const float* bias2 = (const float*)d_in[12];
    const float* Wl3   = (const float*)d_in[13];
    const float* bl3   = (const float*)d_in[14];
    const float* We3   = (const float*)d_in[15];
    const float* att3  = (const float*)d_in[16];
    const float* bias3 = (const float*)d_in[17];

    int N = in_sizes[0] / 128;
    int E = in_sizes[1] / 2;
    float* out = (float*)d_out;

    const int smem1 = (16384 + 128 + 4096) * 4;
    cudaFuncSetAttribute(gemm1_kernel, cudaFuncAttributeMaxDynamicSharedMemorySize, smem1);

    int NB = (N + 255) / 256;

    hist_kernel<<<(E + 255) / 256, 256>>>(ei, E);
    scanA_kernel<<<NB, 256>>>(N);
    scanB_kernel<<<1, 256>>>(NB, N);
    scanC_kernel<<<NB, 256>>>(N);
    scatter_kernel<<<(E + 255) / 256, 256>>>(ei, E);

    gemm1_kernel<<<296, 256, smem1>>>(x, Wl1, bl1, N);
    score1_kernel<<<2368, 256>>>(ea, We1, att1, E);
    agg1_gemm_kernel<<<1184, 256>>>(bias1, Wl2, bl2, Wl3, bl3, N);

    score23_kernel<<<2368, 256>>>(ea, We2, att2, We3, att3, E);
    agg23_kernel<<<1184, 256>>>(bias2, bias3, N);

    finalize_kernel<<<1, 1024>>>(out, N);
}

// round 16
// speedup vs baseline: 1.0768x; 1.0768x over previous
#include <cuda_runtime.h>
#include <math.h>

#define NN 50000
#define EE 800000
#define FULLM 0xFFFFFFFFu

// ---------------- scratch ----------------
__device__ float g_h1[NN * 128];
__device__ float g_h2[NN];
__device__ float g_h3[NN * 32];
__device__ float g_out2[NN];
__device__ float g_out3[NN * 32];
__device__ float g_score1[EE];
__device__ float g_s2a[EE];
__device__ float g_s3a[EE];
__device__ int g_deg[NN];
__device__ int g_rowptr[NN + 1];
__device__ int g_cursor[NN];
__device__ int4 g_edge[EE];      // (src, dst, perm, pad) — one LDG.128 per edge
__device__ int g_srcs[EE];       // separate copy for agg kernels' lane-uniform reads
__device__ int g_bsum[256];
__device__ int g_boff[256];
__device__ unsigned long long g_packed;
__device__ unsigned int g_lmax_ord;
__device__ unsigned int g_key1[2];
__device__ unsigned int g_key2[2];

// ---------------- helpers ----------------
__device__ __forceinline__ float lrelu(float x) { return x >= 0.f ? x : 0.2f * x; }

__device__ __forceinline__ unsigned ordf(float x) {
    unsigned u = __float_as_uint(x);
    return (u & 0x80000000u) ? ~u : (u | 0x80000000u);
}
__device__ __forceinline__ float ordinv(unsigned o) {
    return (o & 0x80000000u) ? __uint_as_float(o & 0x7FFFFFFFu) : __uint_as_float(~o);
}

__device__ __forceinline__ unsigned rotl32(unsigned v, int r) { return (v << r) | (v >> (32 - r)); }

__device__ __forceinline__ void threefry2x32(unsigned k0, unsigned k1, unsigned c0, unsigned c1,
                                             unsigned &o0, unsigned &o1) {
    unsigned ks2 = k0 ^ k1 ^ 0x1BD11BDAu;
    unsigned x0 = c0 + k0, x1 = c1 + k1;
#define TFR(r) { x0 += x1; x1 = rotl32(x1, r); x1 ^= x0; }
    TFR(13) TFR(15) TFR(26) TFR(6)  x0 += k1;  x1 += ks2 + 1u;
    TFR(17) TFR(29) TFR(16) TFR(24) x0 += ks2; x1 += k0 + 2u;
    TFR(13) TFR(15) TFR(26) TFR(6)  x0 += k0;  x1 += k1 + 3u;
    TFR(17) TFR(29) TFR(16) TFR(24) x0 += k1;  x1 += ks2 + 4u;
    TFR(13) TFR(15) TFR(26) TFR(6)  x0 += ks2; x1 += k0 + 5u;
#undef TFR
    o0 = x0; o1 = x1;
}

__device__ __forceinline__ unsigned jax_bits32(unsigned k0, unsigned k1, unsigned i) {
    unsigned o0, o1;
    threefry2x32(k0, k1, 0u, i, o0, o1);
    return o0 ^ o1;
}

__device__ __forceinline__ float gumbel_bits(unsigned bits) {
    float f = __uint_as_float((bits >> 9) | 0x3f800000u) - 1.0f;
    const float TINY = 1.1754943508222875e-38f;
    f = fmaxf(f, TINY);
    return -logf(-logf(f));
}

// ---------------- CSR build ----------------
__global__ void hist_kernel(const int* __restrict__ ei, int E) {
    int e = blockIdx.x * blockDim.x + threadIdx.x;
    if (e < E) atomicAdd(&g_deg[ei[E + e]], 1);
}

__global__ void scanA_kernel(int N) {
    __shared__ int sm[256];
    int t = threadIdx.x, i = blockIdx.x * 256 + t;
    int v = (i < N) ? g_deg[i] : 0;
    sm[t] = v;
    __syncthreads();
    for (int off = 1; off < 256; off <<= 1) {
        int x = (t >= off) ? sm[t - off] : 0;
        __syncthreads();
        sm[t] += x;
        __syncthreads();
    }
    if (i < N) {
        g_rowptr[i] = sm[t] - v;
        g_deg[i] = 0;             // reset for next call (zero-init covers call 1)
    }
    if (t == 255) g_bsum[blockIdx.x] = sm[255];
}

__global__ void scanB_kernel(int NB, int N) {
    __shared__ int sm[256];
    int t = threadIdx.x;
    int v = (t < NB) ? g_bsum[t] : 0;
    sm[t] = v;
    __syncthreads();
    for (int off = 1; off < 256; off <<= 1) {
        int x = (t >= off) ? sm[t - off] : 0;
        __syncthreads();
        sm[t] += x;
        __syncthreads();
    }
    if (t < NB) g_boff[t] = sm[t] - v;
    if (t == 255) g_rowptr[N] = sm[255];
    if (t == 0) {
        g_packed = 0ull;
        g_lmax_ord = 0u;
        unsigned a0, a1, b0, b1;
        threefry2x32(0u, 42u, 0u, 0u, a0, a1);
        threefry2x32(0u, 42u, 0u, 1u, b0, b1);
        g_key1[0] = a0; g_key1[1] = a1;
        g_key2[0] = b0; g_key2[1] = b1;
    }
}

__global__ void scanC_kernel(int N) {
    int i = blockIdx.x * 256 + threadIdx.x;
    if (i < N) {
        int r = g_rowptr[i] + g_boff[blockIdx.x];
        g_rowptr[i] = r;
        g_cursor[i] = r;
    }
}

__global__ void scatter_kernel(const int* __restrict__ ei, int E) {
    int e = blockIdx.x * blockDim.x + threadIdx.x;
    if (e < E) {
        int s = ei[e];
        int d = ei[E + e];
        int pos = atomicAdd(&g_cursor[d], 1);
        g_edge[pos] = make_int4(s, d, e, 0);
        g_srcs[pos] = s;
    }
}

// ---------------- gemm1: h1 = X @ Wl1 + bl1 ----------------
__global__ void gemm1_kernel(const float* __restrict__ X, const float* __restrict__ W,
                             const float* __restrict__ b, int N) {
    extern __shared__ float sm[];
    float* sW = sm;            // 16384
    float* sB = sm + 16384;    // 128
    float* sX = sm + 16512;    // 4096
    int tid = threadIdx.x;
    for (int i = tid; i < 4096; i += blockDim.x)
        reinterpret_cast<float4*>(sW)[i] = reinterpret_cast<const float4*>(W)[i];
    if (tid < 32) reinterpret_cast<float4*>(sB)[tid] = reinterpret_cast<const float4*>(b)[tid];
    __syncthreads();
    int w = tid >> 5, lane = tid & 31;
    int ntiles = (N + 31) / 32;
    for (int tile = blockIdx.x; tile < ntiles; tile += gridDim.x) {
        int row0 = tile * 32;
        for (int i = tid; i < 1024; i += blockDim.x) {
            int rr = i >> 5, c = i & 31;
            int row = row0 + rr;
            float4 v = make_float4(0.f, 0.f, 0.f, 0.f);
            if (row < N) v = reinterpret_cast<const float4*>(X + (size_t)row * 128)[c];
            reinterpret_cast<float4*>(sX)[i] = v;
        }
        __syncthreads();
        float4 a0 = make_float4(0,0,0,0), a1 = a0, a2 = a0, a3 = a0;
#pragma unroll 4
        for (int d = 0; d < 128; d++) {
            float4 wv = reinterpret_cast<float4*>(sW)[d * 32 + lane];
            float x0 = sX[w * 128 + d];
            float x1 = sX[(w + 8) * 128 + d];
            float x2 = sX[(w + 16) * 128 + d];
            float x3 = sX[(w + 24) * 128 + d];
            a0.x = fmaf(x0, wv.x, a0.x); a0.y = fmaf(x0, wv.y, a0.y); a0.z = fmaf(x0, wv.z, a0.z); a0.w = fmaf(x0, wv.w, a0.w);
            a1.x = fmaf(x1, wv.x, a1.x); a1.y = fmaf(x1, wv.y, a1.y); a1.z = fmaf(x1, wv.z, a1.z); a1.w = fmaf(x1, wv.w, a1.w);
            a2.x = fmaf(x2, wv.x, a2.x); a2.y = fmaf(x2, wv.y, a2.y); a2.z = fmaf(x2, wv.z, a2.z); a2.w = fmaf(x2, wv.w, a2.w);
            a3.x = fmaf(x3, wv.x, a3.x); a3.y = fmaf(x3, wv.y, a3.y); a3.z = fmaf(x3, wv.z, a3.z); a3.w = fmaf(x3, wv.w, a3.w);
        }
        float4 b4 = reinterpret_cast<float4*>(sB)[lane];
        float4 accs[4] = {a0, a1, a2, a3};
#pragma unroll
        for (int j = 0; j < 4; j++) {
            int row = row0 + w + 8 * j;
            if (row < N) {
                float4 o = make_float4(accs[j].x + b4.x, accs[j].y + b4.y,
                                       accs[j].z + b4.z, accs[j].w + b4.w);
                reinterpret_cast<float4*>(g_h1 + (size_t)row * 128)[lane] = o;
            }
        }
        __syncthreads();
    }
}

// ---------------- layer-1 edge scores: 2 edges per warp-iter, packed edge records ----------------
__global__ void score1_kernel(const float* __restrict__ ea, const float* __restrict__ We,
                              const float* __restrict__ att, int E) {
    __shared__ float4 sW[16 * 32];
    __shared__ float4 sAtt[32];
    int tid = threadIdx.x;
    for (int i = tid; i < 16 * 32; i += blockDim.x)
        sW[i] = reinterpret_cast<const float4*>(We)[i];
    if (tid < 32) sAtt[tid] = reinterpret_cast<const float4*>(att)[tid];
    __syncthreads();
    int lane = tid & 31;
    int wid = (blockIdx.x * blockDim.x + tid) >> 5;
    int NW = (gridDim.x * blockDim.x) >> 5;
    float4 at = sAtt[lane];
    for (int pos = wid * 2; pos < E; pos += NW * 2) {
        bool ok1 = (pos + 1 < E);
        int pb = ok1 ? pos + 1 : pos;
        int4 E0 = g_edge[pos];
        int4 E1 = g_edge[pb];
        int s0 = E0.x, d0 = E0.y, e0 = E0.z;
        int s1 = E1.x, d1 = E1.y, e1 = E1.z;
        float4 hj0 = reinterpret_cast<const float4*>(g_h1 + (size_t)s0 * 128)[lane];
        float4 hi0 = reinterpret_cast<const float4*>(g_h1 + (size_t)d0 * 128)[lane];
        float4 hj1 = reinterpret_cast<const float4*>(g_h1 + (size_t)s1 * 128)[lane];
        float4 hi1 = reinterpret_cast<const float4*>(g_h1 + (size_t)d1 * 128)[lane];
        const float4* eaA = reinterpret_cast<const float4*>(ea + (size_t)e0 * 16);
        const float4* eaB = reinterpret_cast<const float4*>(ea + (size_t)e1 * 16);
        float ev0[16], ev1[16];
#pragma unroll
        for (int j = 0; j < 4; j++) {
            float4 t0 = __ldg(eaA + j);
            float4 t1 = __ldg(eaB + j);
            ev0[4*j+0]=t0.x; ev0[4*j+1]=t0.y; ev0[4*j+2]=t0.z; ev0[4*j+3]=t0.w;
            ev1[4*j+0]=t1.x; ev1[4*j+1]=t1.y; ev1[4*j+2]=t1.z; ev1[4*j+3]=t1.w;
        }
        float4 c0 = make_float4(0,0,0,0), c1 = make_float4(0,0,0,0);
#pragma unroll
        for (int d = 0; d < 16; d++) {
            float4 w = sW[d * 32 + lane];
            c0.x = fmaf(ev0[d], w.x, c0.x); c0.y = fmaf(ev0[d], w.y, c0.y);
            c0.z = fmaf(ev0[d], w.z, c0.z); c0.w = fmaf(ev0[d], w.w, c0.w);
            c1.x = fmaf(ev1[d], w.x, c1.x); c1.y = fmaf(ev1[d], w.y, c1.y);
            c1.z = fmaf(ev1[d], w.z, c1.z); c1.w = fmaf(ev1[d], w.w, c1.w);
        }
        float p0 = at.x * lrelu(hi0.x + hj0.x + c0.x)
                 + at.y * lrelu(hi0.y + hj0.y + c0.y)
                 + at.z * lrelu(hi0.z + hj0.z + c0.z)
                 + at.w * lrelu(hi0.w + hj0.w + c0.w);
        float p1 = at.x * lrelu(hi1.x + hj1.x + c1.x)
                 + at.y * lrelu(hi1.y + hj1.y + c1.y)
                 + at.z * lrelu(hi1.z + hj1.z + c1.z)
                 + at.w * lrelu(hi1.w + hj1.w + c1.w);
#pragma unroll
        for (int o = 16; o; o >>= 1) {
            p0 += __shfl_xor_sync(FULLM, p0, o);
            p1 += __shfl_xor_sync(FULLM, p1, o);
        }
        if (lane == 0) {
            g_score1[pos] = p0;
            if (ok1) g_score1[pos + 1] = p1;
        }
    }
}

// ---------------- fused layer-1 softmax/aggregate + gemm23 ----------------
__global__ void agg1_gemm_kernel(const float* __restrict__ bias1,
                                 const float* __restrict__ Wl2, const float* __restrict__ bl2,
                                 const float* __restrict__ Wl3, const float* __restrict__ bl3, int N) {
    __shared__ float sW[128 * 34];   // k<32: Wl3[d][k], k==32: Wl2[d]
    __shared__ float4 sB1[32];
    int tid = threadIdx.x;
    for (int i = tid; i < 128 * 33; i += blockDim.x) {
        int d = i / 33, k = i % 33;
        sW[d * 34 + k] = (k < 32) ? Wl3[d * 32 + k] : Wl2[d];
    }
    if (tid < 32) sB1[tid] = reinterpret_cast<const float4*>(bias1)[tid];
    __syncthreads();
    int lane = tid & 31;
    int wid = (blockIdx.x * blockDim.x + tid) >> 5;
    int nw = (gridDim.x * blockDim.x) >> 5;
    float b2 = __ldg(bl2);
    float b3 = __ldg(bl3 + lane);
    for (int i = wid; i < N; i += nw) {
        int beg = g_rowptr[i], end = g_rowptr[i + 1];
        int deg = end - beg;
        int p0 = beg + lane, p1 = beg + 32 + lane;
        bool a0 = p0 < end, a1 = p1 < end;
        float s0 = a0 ? g_score1[p0] : -INFINITY;
        float s1 = a1 ? g_score1[p1] : -INFINITY;
        int i0 = a0 ? g_srcs[p0] : 0;
        int i1 = a1 ? g_srcs[p1] : 0;
        float m = fmaxf(s0, s1);
        for (int p = beg + 64 + lane; p < end; p += 32) m = fmaxf(m, g_score1[p]);
#pragma unroll
        for (int o = 16; o; o >>= 1) m = fmaxf(m, __shfl_xor_sync(FULLM, m, o));
        float e0 = a0 ? expf(s0 - m) : 0.f;
        float e1 = a1 ? expf(s1 - m) : 0.f;
        float den = e0 + e1;
        for (int p = beg + 64 + lane; p < end; p += 32) den += expf(g_score1[p] - m);
#pragma unroll
        for (int o = 16; o; o >>= 1) den += __shfl_xor_sync(FULLM, den, o);
        float inv = 1.0f / (den + 1e-16f);
        float4 acc = make_float4(0.f, 0.f, 0.f, 0.f);
        int dmain = deg < 64 ? deg : 64;
        int k = 0;
        for (; k + 8 <= dmain; k += 8) {
            int   ss[8]; float ww[8];
#pragma unroll
            for (int j = 0; j < 8; j++) {
                ss[j] = __shfl_sync(FULLM, (k + j < 32) ? i0 : i1, (k + j) & 31);
                ww[j] = __shfl_sync(FULLM, (k + j < 32) ? e0 : e1, (k + j) & 31);
            }
            float4 vv[8];
#pragma unroll
            for (int j = 0; j < 8; j++)
                vv[j] = reinterpret_cast<const float4*>(g_h1 + (size_t)ss[j] * 128)[lane];
#pragma unroll
            for (int j = 0; j < 8; j++) {
                float aw = ww[j] * inv;
                acc.x = fmaf(aw, vv[j].x, acc.x);
                acc.y = fmaf(aw, vv[j].y, acc.y);
                acc.z = fmaf(aw, vv[j].z, acc.z);
                acc.w = fmaf(aw, vv[j].w, acc.w);
            }
        }
        for (; k + 4 <= dmain; k += 4) {
            int   ss[4]; float ww[4];
#pragma unroll
            for (int j = 0; j < 4; j++) {
                ss[j] = __shfl_sync(FULLM, (k + j < 32) ? i0 : i1, (k + j) & 31);
                ww[j] = __shfl_sync(FULLM, (k + j < 32) ? e0 : e1, (k + j) & 31);
            }
            float4 vv[4];
#pragma unroll
            for (int j = 0; j < 4; j++)
                vv[j] = reinterpret_cast<const float4*>(g_h1 + (size_t)ss[j] * 128)[lane];
#pragma unroll
            for (int j = 0; j < 4; j++) {
                float aw = ww[j] * inv;
                acc.x = fmaf(aw, vv[j].x, acc.x);
                acc.y = fmaf(aw, vv[j].y, acc.y);
                acc.z = fmaf(aw, vv[j].z, acc.z);
                acc.w = fmaf(aw, vv[j].w, acc.w);
            }
        }
        for (; k < dmain; k++) {
            int src  = __shfl_sync(FULLM, (k < 32) ? i0 : i1, k & 31);
            float ee = __shfl_sync(FULLM, (k < 32) ? e0 : e1, k & 31);
            float aw = ee * inv;
            float4 v = reinterpret_cast<const float4*>(g_h1 + (size_t)src * 128)[lane];
            acc.x = fmaf(aw, v.x, acc.x);
            acc.y = fmaf(aw, v.y, acc.y);
            acc.z = fmaf(aw, v.z, acc.z);
            acc.w = fmaf(aw, v.w, acc.w);
        }
        for (int p = beg + 64; p < end; p++) {
            float aw = expf(g_score1[p] - m) * inv;
            float4 v = reinterpret_cast<const float4*>(g_h1 + (size_t)g_srcs[p] * 128)[lane];
            acc.x = fmaf(aw, v.x, acc.x);
            acc.y = fmaf(aw, v.y, acc.y);
            acc.z = fmaf(aw, v.z, acc.z);
            acc.w = fmaf(aw, v.w, acc.w);
        }
        float4 bb = sB1[lane];
        float4 lr = make_float4(acc.x + bb.x, acc.y + bb.y, acc.z + bb.z, acc.w + bb.w);
        float acc3 = 0.f, acc2 = 0.f;
#pragma unroll
        for (int d = 0; d < 128; d++) {
            int r = d & 3;
            float comp = (r == 0) ? lr.x : (r == 1) ? lr.y : (r == 2) ? lr.z : lr.w;
            float v = __shfl_sync(FULLM, comp, d >> 2);
            acc3 = fmaf(v, sW[d * 34 + lane], acc3);
            acc2 = fmaf(v, sW[d * 34 + 32], acc2);
        }
        g_h3[(size_t)i * 32 + lane] = acc3 + b3;
        if (lane == 0) g_h2[i] = acc2 + b2;
    }
}

// ---------------- fused layer-2+3 edge scores: 2 edges per warp-iter, packed records ----------------
__global__ void score23_kernel(const float* __restrict__ ea,
                               const float* __restrict__ We2, const float* __restrict__ att2,
                               const float* __restrict__ We3, const float* __restrict__ att3, int E) {
    __shared__ float sW3[16 * 32];
    __shared__ float sW2[16];
    __shared__ float sA3[32];
    int tid = threadIdx.x;
    for (int i = tid; i < 16 * 32; i += blockDim.x) sW3[i] = We3[i];
    if (tid < 16) sW2[tid] = We2[tid];
    if (tid < 32) sA3[tid] = att3[tid];
    __syncthreads();
    int lane = tid & 31;
    int wid = (blockIdx.x * blockDim.x + tid) >> 5;
    int NW = (gridDim.x * blockDim.x) >> 5;
    float a2 = __ldg(att2);
    float at3 = sA3[lane];
    for (int pos = wid * 2; pos < E; pos += NW * 2) {
        bool ok1 = (pos + 1 < E);
        int pb = ok1 ? pos + 1 : pos;
        int4 E0 = g_edge[pos];
        int4 E1 = g_edge[pb];
        int s0 = E0.x, d0 = E0.y, e0 = E0.z;
        int s1 = E1.x, d1 = E1.y, e1 = E1.z;
        float h2j0 = __ldg(&g_h2[s0]), h2i0 = __ldg(&g_h2[d0]);
        float h2j1 = __ldg(&g_h2[s1]), h2i1 = __ldg(&g_h2[d1]);
        float h3j0 = g_h3[(size_t)s0 * 32 + lane];
        float h3i0 = g_h3[(size_t)d0 * 32 + lane];
        float h3j1 = g_h3[(size_t)s1 * 32 + lane];
        float h3i1 = g_h3[(size_t)d1 * 32 + lane];
        const float4* eaA = reinterpret_cast<const float4*>(ea + (size_t)e0 * 16);
        const float4* eaB = reinterpret_cast<const float4*>(ea + (size_t)e1 * 16);
        float ev0[16], ev1[16];
#pragma unroll
        for (int j = 0; j < 4; j++) {
            float4 t0 = __ldg(eaA + j);
            float4 t1 = __ldg(eaB + j);
            ev0[4*j+0]=t0.x; ev0[4*j+1]=t0.y; ev0[4*j+2]=t0.z; ev0[4*j+3]=t0.w;
            ev1[4*j+0]=t1.x; ev1[4*j+1]=t1.y; ev1[4*j+2]=t1.z; ev1[4*j+3]=t1.w;
        }
        float e30 = 0.f, e20 = 0.f, e31 = 0.f, e21 = 0.f;
#pragma unroll
        for (int d = 0; d < 16; d++) {
            float w3 = sW3[d * 32 + lane];
            float w2 = sW2[d];
            e30 = fmaf(ev0[d], w3, e30);
            e31 = fmaf(ev1[d], w3, e31);
            e20 = fmaf(ev0[d], w2, e20);
            e21 = fmaf(ev1[d], w2, e21);
        }
        float p30 = at3 * lrelu(h3i0 + h3j0 + e30);
        float p31 = at3 * lrelu(h3i1 + h3j1 + e31);
#pragma unroll
        for (int o = 16; o; o >>= 1) {
            p30 += __shfl_xor_sync(FULLM, p30, o);
            p31 += __shfl_xor_sync(FULLM, p31, o);
        }
        float q0 = a2 * lrelu(h2i0 + h2j0 + e20);
        float q1 = a2 * lrelu(h2i1 + h2j1 + e21);
        if (lane == 0) {
            g_s2a[pos] = q0;
            g_s3a[pos] = p30;
            if (ok1) { g_s2a[pos + 1] = q1; g_s3a[pos + 1] = p31; }
        }
    }
}

// ---------------- fused layer-2+3 softmax/aggregate + node gumbel sampling ----------------
__global__ void agg23_kernel(const float* __restrict__ bias2, const float* __restrict__ bias3, int N) {
    __shared__ unsigned long long sPk[8];
    __shared__ unsigned sLo[8];
    int tid = threadIdx.x;
    int lane = tid & 31;
    int warp = tid >> 5;
    int wid = (blockIdx.x * blockDim.x + tid) >> 5;
    int nw = (gridDim.x * blockDim.x) >> 5;
    float b2 = __ldg(bias2);
    float b3 = __ldg(bias3 + lane);
    unsigned gk0 = g_key1[0], gk1 = g_key1[1];
    unsigned long long bestPk = 0ull;
    unsigned bestLo = 0u;
    for (int i = wid; i < N; i += nw) {
        int beg = g_rowptr[i], end = g_rowptr[i + 1];
        int deg = end - beg;
        int p0 = beg + lane, p1 = beg + 32 + lane;
        bool a0 = p0 < end, a1 = p1 < end;
        float s20 = a0 ? g_s2a[p0] : -INFINITY;
        float s30 = a0 ? g_s3a[p0] : -INFINITY;
        float s21 = a1 ? g_s2a[p1] : -INFINITY;
        float s31 = a1 ? g_s3a[p1] : -INFINITY;
        int i0 = a0 ? g_srcs[p0] : 0;
        int i1 = a1 ? g_srcs[p1] : 0;
        float m2 = fmaxf(s20, s21), m3 = fmaxf(s30, s31);
        for (int p = beg + 64 + lane; p < end; p += 32) {
            m2 = fmaxf(m2, g_s2a[p]);
            m3 = fmaxf(m3, g_s3a[p]);
        }
#pragma unroll
        for (int o = 16; o; o >>= 1) {
            m2 = fmaxf(m2, __shfl_xor_sync(FULLM, m2, o));
            m3 = fmaxf(m3, __shfl_xor_sync(FULLM, m3, o));
        }
        float e20 = a0 ? expf(s20 - m2) : 0.f;
        float e21 = a1 ? expf(s21 - m2) : 0.f;
        float e30 = a0 ? expf(s30 - m3) : 0.f;
        float e31 = a1 ? expf(s31 - m3) : 0.f;
        float den2 = e20 + e21;
        float den3 = e30 + e31;
        float num2 = e20 * (a0 ? __ldg(&g_h2[i0]) : 0.f)
                   + e21 * (a1 ? __ldg(&g_h2[i1]) : 0.f);
        for (int p = beg + 64 + lane; p < end; p += 32) {
            float e2 = expf(g_s2a[p] - m2);
            den2 += e2;
            num2 += e2 * __ldg(&g_h2[g_srcs[p]]);
            den3 += expf(g_s3a[p] - m3);
        }
#pragma unroll
        for (int o = 16; o; o >>= 1) {
            den2 += __shfl_xor_sync(FULLM, den2, o);
            num2 += __shfl_xor_sync(FULLM, num2, o);
            den3 += __shfl_xor_sync(FULLM, den3, o);
        }
        float inv3 = 1.0f / (den3 + 1e-16f);
        float acc = 0.f;
        int dmain = deg < 64 ? deg : 64;
        int k = 0;
        for (; k + 8 <= dmain; k += 8) {
            int ss[8]; float ww[8];
#pragma unroll
            for (int j = 0; j < 8; j++) {
                ss[j] = __shfl_sync(FULLM, (k + j < 32) ? i0 : i1, (k + j) & 31);
                ww[j] = __shfl_sync(FULLM, (k + j < 32) ? e30 : e31, (k + j) & 31);
            }
            float vv[8];
#pragma unroll
            for (int j = 0; j < 8; j++)
                vv[j] = g_h3[(size_t)ss[j] * 32 + lane];
#pragma unroll
            for (int j = 0; j < 8; j++)
                acc = fmaf(ww[j] * inv3, vv[j], acc);
        }
        for (; k + 4 <= dmain; k += 4) {
            int ss[4]; float ww[4];
#pragma unroll
            for (int j = 0; j < 4; j++) {
                ss[j] = __shfl_sync(FULLM, (k + j < 32) ? i0 : i1, (k + j) & 31);
                ww[j] = __shfl_sync(FULLM, (k + j < 32) ? e30 : e31, (k + j) & 31);
            }
            float vv[4];
#pragma unroll
            for (int j = 0; j < 4; j++)
                vv[j] = g_h3[(size_t)ss[j] * 32 + lane];
#pragma unroll
            for (int j = 0; j < 4; j++)
                acc = fmaf(ww[j] * inv3, vv[j], acc);
        }
        for (; k < dmain; k++) {
            int src  = __shfl_sync(FULLM, (k < 32) ? i0 : i1, k & 31);
            float ee = __shfl_sync(FULLM, (k < 32) ? e30 : e31, k & 31);
            acc = fmaf(ee * inv3, g_h3[(size_t)src * 32 + lane], acc);
        }
        for (int p = beg + 64; p < end; p++) {
            float aw = expf(g_s3a[p] - m3) * inv3;
            acc = fmaf(aw, g_h3[(size_t)g_srcs[p] * 32 + lane], acc);
        }
        g_out3[(size_t)i * 32 + lane] = acc + b3;
        if (lane == 0) {
            float lg = num2 / (den2 + 1e-16f) + b2;
            g_out2[i] = lg;
            unsigned bits = jax_bits32(gk0, gk1, (unsigned)i);
            float z = lg + gumbel_bits(bits);
            unsigned long long pk = ((unsigned long long)ordf(z) << 32)
                                  | (unsigned long long)(0xFFFFFFFFu - (unsigned)i);
            if (pk > bestPk) bestPk = pk;
            unsigned lo = ordf(lg);
            if (lo > bestLo) bestLo = lo;
        }
    }
    if (lane == 0) { sPk[warp] = bestPk; sLo[warp] = bestLo; }
    __syncthreads();
    if (tid == 0) {
        unsigned long long bp = sPk[0];
        unsigned bl = sLo[0];
#pragma unroll
        for (int j = 1; j < 8; j++) {
            if (sPk[j] > bp) bp = sPk[j];
            if (sLo[j] > bl) bl = sLo[j];
        }
        atomicMax(&g_packed, bp);
        atomicMax(&g_lmax_ord, bl);
    }
}

// ---------------- finalize: sumexp + node_lp + action sampling ----------------
__global__ void finalize_kernel(float* __restrict__ out, int N) {
    __shared__ float ssum[32];
    int tid = threadIdx.x;
    int lane = tid & 31;
    int warp = tid >> 5;
    float lmax = ordinv(g_lmax_ord);
    float s = 0.f;
    for (int i = tid; i < N; i += 1024) s += expf(g_out2[i] - lmax);
#pragma unroll
    for (int o = 16; o; o >>= 1) s += __shfl_xor_sync(FULLM, s, o);
    if (lane == 0) ssum[warp] = s;
    __syncthreads();
    if (tid < 32) {
        float v = ssum[tid];
#pragma unroll
        for (int o = 16; o; o >>= 1) v += __shfl_xor_sync(FULLM, v, o);
        if (tid == 0) ssum[0] = v;
    }
    __syncthreads();
    float S = ssum[0];
    if (tid < 32) {
        unsigned long long pk = g_packed;
        unsigned sel = 0xFFFFFFFFu - (unsigned)(pk & 0xFFFFFFFFull);
        float node_lp = g_out2[sel] - lmax - logf(S);

        float logit = g_out3[(size_t)sel * 32 + lane];
        unsigned bits = jax_bits32(g_key2[0], g_key2[1], (unsigned)lane);
        float z = logit + gumbel_bits(bits);

        float bz = z;
        int bi = lane;
#pragma unroll
        for (int o = 16; o; o >>= 1) {
            float oz = __shfl_xor_sync(FULLM, bz, o);
            int oi = __shfl_xor_sync(FULLM, bi, o);
            if (oz > bz || (oz == bz && oi < bi)) { bz = oz; bi = oi; }
        }
        float m = logit;
#pragma unroll
        for (int o = 16; o; o >>= 1) m = fmaxf(m, __shfl_xor_sync(FULLM, m, o));
        float se = expf(logit - m);
#pragma unroll
        for (int o = 16; o; o >>= 1) se += __shfl_xor_sync(FULLM, se, o);
        float sel_logit = __shfl_sync(FULLM, logit, bi);
        float action_lp = sel_logit - m - logf(se);
        if (lane == 0) {
            out[0] = (float)sel;
            out[1] = (float)bi;
            out[2] = node_lp + action_lp;
        }
    }
}

// ---------------- launch ----------------
extern "C" void kernel_launch(void* const* d_in, const int* in_sizes, int n_in,
                              void* d_out, int out_size) {
    const float* x     = (const float*)d_in[0];
    const int*   ei    = (const int*)d_in[1];
    const float* ea    = (const float*)d_in[2];
    const float* Wl1   = (const float*)d_in[3];
    const float* bl1   = (const float*)d_in[4];
    const float* We1   = (const float*)d_in[5];
    const float* att1  = (const float*)d_in[6];
    const float* bias1 = (const float*)d_in[7];
    const float* Wl2   = (const float*)d_in[8];
    const float* bl2   = (const float*)d_in[9];
    const float* We2   = (const float*)d_in[10];
    const float* att2  = (const float*)d_in[11];
    const float* bias2 = (const float*)d_in[12];
    const float* Wl3   = (const float*)d_in[13];
    const float* bl3   = (const float*)d_in[14];
    const float* We3   = (const float*)d_in[15];
    const float* att3  = (const float*)d_in[16];
    const float* bias3 = (const float*)d_in[17];

    int N = in_sizes[0] / 128;
    int E = in_sizes[1] / 2;
    float* out = (float*)d_out;

    const int smem1 = (16384 + 128 + 4096) * 4;
    cudaFuncSetAttribute(gemm1_kernel, cudaFuncAttributeMaxDynamicSharedMemorySize, smem1);

    int NB = (N + 255) / 256;

    // Fork: gemm1 (depends only on x, Wl1) runs on side stream, overlapping the
    // CSR build chain on the main (capture) stream.
    cudaStream_t s2;
    cudaEvent_t evFork, evJoin;
    cudaStreamCreateWithFlags(&s2, cudaStreamNonBlocking);
    cudaEventCreateWithFlags(&evFork, cudaEventDisableTiming);
    cudaEventCreateWithFlags(&evJoin, cudaEventDisableTiming);

    cudaEventRecord(evFork, 0);
    cudaStreamWaitEvent(s2, evFork, 0);
    gemm1_kernel<<<296, 256, smem1, s2>>>(x, Wl1, bl1, N);
    cudaEventRecord(evJoin, s2);

    hist_kernel<<<(E + 255) / 256, 256>>>(ei, E);
    scanA_kernel<<<NB, 256>>>(N);
    scanB_kernel<<<1, 256>>>(NB, N);
    scanC_kernel<<<NB, 256>>>(N);
    scatter_kernel<<<(E + 255) / 256, 256>>>(ei, E);

    cudaStreamWaitEvent(0, evJoin, 0);

    score1_kernel<<<2368, 256>>>(ea, We1, att1, E);
    agg1_gemm_kernel<<<1184, 256>>>(bias1, Wl2, bl2, Wl3, bl3, N);

    score23_kernel<<<2368, 256>>>(ea, We2, att2, We3, att3, E);
    agg23_kernel<<<1184, 256>>>(bias2, bias3, N);

    finalize_kernel<<<1, 1024>>>(out, N);

    cudaStreamDestroy(s2);
    cudaEventDestroy(evFork);
    cudaEventDestroy(evJoin);
}

// round 17
// speedup vs baseline: 1.0871x; 1.0096x over previous
#include <cuda_runtime.h>
#include <math.h>

#define NN 50000
#define EE 800000
#define FULLM 0xFFFFFFFFu

// ---------------- scratch ----------------
__device__ float g_h1[NN * 128];
__device__ float g_h2[NN];
__device__ float g_h3[NN * 32];
__device__ float g_out2[NN];
__device__ float g_out3[NN * 32];
__device__ float g_score1[EE];
__device__ float g_s2a[EE];
__device__ float g_s3a[EE];
__device__ int g_deg[NN];
__device__ int g_rowptr[NN + 1];
__device__ int g_cursor[NN];
__device__ int4 g_edge[EE];      // (src, dst, perm, pad) — one LDG.128 per edge
__device__ int g_srcs[EE];       // separate copy for agg kernels' lane-uniform reads
__device__ int g_bsum[256];
__device__ int g_boff[256];
__device__ unsigned long long g_packed;
__device__ unsigned int g_lmax_ord;
__device__ unsigned int g_key1[2];
__device__ unsigned int g_key2[2];

// ---------------- helpers ----------------
__device__ __forceinline__ float lrelu(float x) { return x >= 0.f ? x : 0.2f * x; }

__device__ __forceinline__ unsigned ordf(float x) {
    unsigned u = __float_as_uint(x);
    return (u & 0x80000000u) ? ~u : (u | 0x80000000u);
}
__device__ __forceinline__ float ordinv(unsigned o) {
    return (o & 0x80000000u) ? __uint_as_float(o & 0x7FFFFFFFu) : __uint_as_float(~o);
}

__device__ __forceinline__ unsigned rotl32(unsigned v, int r) { return (v << r) | (v >> (32 - r)); }

__device__ __forceinline__ void threefry2x32(unsigned k0, unsigned k1, unsigned c0, unsigned c1,
                                             unsigned &o0, unsigned &o1) {
    unsigned ks2 = k0 ^ k1 ^ 0x1BD11BDAu;
    unsigned x0 = c0 + k0, x1 = c1 + k1;
#define TFR(r) { x0 += x1; x1 = rotl32(x1, r); x1 ^= x0; }
    TFR(13) TFR(15) TFR(26) TFR(6)  x0 += k1;  x1 += ks2 + 1u;
    TFR(17) TFR(29) TFR(16) TFR(24) x0 += ks2; x1 += k0 + 2u;
    TFR(13) TFR(15) TFR(26) TFR(6)  x0 += k0;  x1 += k1 + 3u;
    TFR(17) TFR(29) TFR(16) TFR(24) x0 += k1;  x1 += ks2 + 4u;
    TFR(13) TFR(15) TFR(26) TFR(6)  x0 += ks2; x1 += k0 + 5u;
#undef TFR
    o0 = x0; o1 = x1;
}

__device__ __forceinline__ unsigned jax_bits32(unsigned k0, unsigned k1, unsigned i) {
    unsigned o0, o1;
    threefry2x32(k0, k1, 0u, i, o0, o1);
    return o0 ^ o1;
}

__device__ __forceinline__ float gumbel_bits(unsigned bits) {
    float f = __uint_as_float((bits >> 9) | 0x3f800000u) - 1.0f;
    const float TINY = 1.1754943508222875e-38f;
    f = fmaxf(f, TINY);
    return -logf(-logf(f));
}

// ---------------- CSR build ----------------
__global__ void hist_kernel(const int* __restrict__ ei, int E) {
    int e = blockIdx.x * blockDim.x + threadIdx.x;
    if (e < E) atomicAdd(&g_deg[ei[E + e]], 1);
}

__global__ void scanA_kernel(int N) {
    __shared__ int sm[256];
    int t = threadIdx.x, i = blockIdx.x * 256 + t;
    int v = (i < N) ? g_deg[i] : 0;
    sm[t] = v;
    __syncthreads();
    for (int off = 1; off < 256; off <<= 1) {
        int x = (t >= off) ? sm[t - off] : 0;
        __syncthreads();
        sm[t] += x;
        __syncthreads();
    }
    if (i < N) {
        g_rowptr[i] = sm[t] - v;
        g_deg[i] = 0;             // reset for next call (zero-init covers call 1)
    }
    if (t == 255) g_bsum[blockIdx.x] = sm[255];
}

__global__ void scanB_kernel(int NB, int N) {
    __shared__ int sm[256];
    int t = threadIdx.x;
    int v = (t < NB) ? g_bsum[t] : 0;
    sm[t] = v;
    __syncthreads();
    for (int off = 1; off < 256; off <<= 1) {
        int x = (t >= off) ? sm[t - off] : 0;
        __syncthreads();
        sm[t] += x;
        __syncthreads();
    }
    if (t < NB) g_boff[t] = sm[t] - v;
    if (t == 255) g_rowptr[N] = sm[255];
    if (t == 0) {
        g_packed = 0ull;
        g_lmax_ord = 0u;
        unsigned a0, a1, b0, b1;
        threefry2x32(0u, 42u, 0u, 0u, a0, a1);
        threefry2x32(0u, 42u, 0u, 1u, b0, b1);
        g_key1[0] = a0; g_key1[1] = a1;
        g_key2[0] = b0; g_key2[1] = b1;
    }
}

__global__ void scanC_kernel(int N) {
    int i = blockIdx.x * 256 + threadIdx.x;
    if (i < N) {
        int r = g_rowptr[i] + g_boff[blockIdx.x];
        g_rowptr[i] = r;
        g_cursor[i] = r;
    }
}

__global__ void scatter_kernel(const int* __restrict__ ei, int E) {
    int e = blockIdx.x * blockDim.x + threadIdx.x;
    if (e < E) {
        int s = ei[e];
        int d = ei[E + e];
        int pos = atomicAdd(&g_cursor[d], 1);
        g_edge[pos] = make_int4(s, d, e, 0);
        g_srcs[pos] = s;
    }
}

// ---------------- gemm1: h1 = X @ Wl1 + bl1 ----------------
__global__ void gemm1_kernel(const float* __restrict__ X, const float* __restrict__ W,
                             const float* __restrict__ b, int N) {
    extern __shared__ float sm[];
    float* sW = sm;            // 16384
    float* sB = sm + 16384;    // 128
    float* sX = sm + 16512;    // 4096
    int tid = threadIdx.x;
    for (int i = tid; i < 4096; i += blockDim.x)
        reinterpret_cast<float4*>(sW)[i] = reinterpret_cast<const float4*>(W)[i];
    if (tid < 32) reinterpret_cast<float4*>(sB)[tid] = reinterpret_cast<const float4*>(b)[tid];
    __syncthreads();
    int w = tid >> 5, lane = tid & 31;
    int ntiles = (N + 31) / 32;
    for (int tile = blockIdx.x; tile < ntiles; tile += gridDim.x) {
        int row0 = tile * 32;
        for (int i = tid; i < 1024; i += blockDim.x) {
            int rr = i >> 5, c = i & 31;
            int row = row0 + rr;
            float4 v = make_float4(0.f, 0.f, 0.f, 0.f);
            if (row < N) v = reinterpret_cast<const float4*>(X + (size_t)row * 128)[c];
            reinterpret_cast<float4*>(sX)[i] = v;
        }
        __syncthreads();
        float4 a0 = make_float4(0,0,0,0), a1 = a0, a2 = a0, a3 = a0;
#pragma unroll 4
        for (int d = 0; d < 128; d++) {
            float4 wv = reinterpret_cast<float4*>(sW)[d * 32 + lane];
            float x0 = sX[w * 128 + d];
            float x1 = sX[(w + 8) * 128 + d];
            float x2 = sX[(w + 16) * 128 + d];
            float x3 = sX[(w + 24) * 128 + d];
            a0.x = fmaf(x0, wv.x, a0.x); a0.y = fmaf(x0, wv.y, a0.y); a0.z = fmaf(x0, wv.z, a0.z); a0.w = fmaf(x0, wv.w, a0.w);
            a1.x = fmaf(x1, wv.x, a1.x); a1.y = fmaf(x1, wv.y, a1.y); a1.z = fmaf(x1, wv.z, a1.z); a1.w = fmaf(x1, wv.w, a1.w);
            a2.x = fmaf(x2, wv.x, a2.x); a2.y = fmaf(x2, wv.y, a2.y); a2.z = fmaf(x2, wv.z, a2.z); a2.w = fmaf(x2, wv.w, a2.w);
            a3.x = fmaf(x3, wv.x, a3.x); a3.y = fmaf(x3, wv.y, a3.y); a3.z = fmaf(x3, wv.z, a3.z); a3.w = fmaf(x3, wv.w, a3.w);
        }
        float4 b4 = reinterpret_cast<float4*>(sB)[lane];
        float4 accs[4] = {a0, a1, a2, a3};
#pragma unroll
        for (int j = 0; j < 4; j++) {
            int row = row0 + w + 8 * j;
            if (row < N) {
                float4 o = make_float4(accs[j].x + b4.x, accs[j].y + b4.y,
                                       accs[j].z + b4.z, accs[j].w + b4.w);
                reinterpret_cast<float4*>(g_h1 + (size_t)row * 128)[lane] = o;
            }
        }
        __syncthreads();
    }
}

// ---------------- layer-1 edge scores: 2 edges per warp-iter, occupancy-forced ----------------
__global__ void __launch_bounds__(256, 4) score1_kernel(const float* __restrict__ ea,
                              const float* __restrict__ We,
                              const float* __restrict__ att, int E) {
    __shared__ float4 sW[16 * 32];
    __shared__ float4 sAtt[32];
    int tid = threadIdx.x;
    for (int i = tid; i < 16 * 32; i += blockDim.x)
        sW[i] = reinterpret_cast<const float4*>(We)[i];
    if (tid < 32) sAtt[tid] = reinterpret_cast<const float4*>(att)[tid];
    __syncthreads();
    int lane = tid & 31;
    int wid = (blockIdx.x * blockDim.x + tid) >> 5;
    int NW = (gridDim.x * blockDim.x) >> 5;
    float4 at = sAtt[lane];
    for (int pos = wid * 2; pos < E; pos += NW * 2) {
        bool ok1 = (pos + 1 < E);
        int pb = ok1 ? pos + 1 : pos;
        int4 E0 = g_edge[pos];
        int4 E1 = g_edge[pb];
        int s0 = E0.x, d0 = E0.y, e0 = E0.z;
        int s1 = E1.x, d1 = E1.y, e1 = E1.z;
        float4 hj0 = reinterpret_cast<const float4*>(g_h1 + (size_t)s0 * 128)[lane];
        float4 hi0 = reinterpret_cast<const float4*>(g_h1 + (size_t)d0 * 128)[lane];
        float4 hj1 = reinterpret_cast<const float4*>(g_h1 + (size_t)s1 * 128)[lane];
        float4 hi1 = reinterpret_cast<const float4*>(g_h1 + (size_t)d1 * 128)[lane];
        const float4* eaA = reinterpret_cast<const float4*>(ea + (size_t)e0 * 16);
        const float4* eaB = reinterpret_cast<const float4*>(ea + (size_t)e1 * 16);
        float ev0[16], ev1[16];
#pragma unroll
        for (int j = 0; j < 4; j++) {
            float4 t0 = __ldg(eaA + j);
            float4 t1 = __ldg(eaB + j);
            ev0[4*j+0]=t0.x; ev0[4*j+1]=t0.y; ev0[4*j+2]=t0.z; ev0[4*j+3]=t0.w;
            ev1[4*j+0]=t1.x; ev1[4*j+1]=t1.y; ev1[4*j+2]=t1.z; ev1[4*j+3]=t1.w;
        }
        float4 c0 = make_float4(0,0,0,0), c1 = make_float4(0,0,0,0);
#pragma unroll
        for (int d = 0; d < 16; d++) {
            float4 w = sW[d * 32 + lane];
            c0.x = fmaf(ev0[d], w.x, c0.x); c0.y = fmaf(ev0[d], w.y, c0.y);
            c0.z = fmaf(ev0[d], w.z, c0.z); c0.w = fmaf(ev0[d], w.w, c0.w);
            c1.x = fmaf(ev1[d], w.x, c1.x); c1.y = fmaf(ev1[d], w.y, c1.y);
            c1.z = fmaf(ev1[d], w.z, c1.z); c1.w = fmaf(ev1[d], w.w, c1.w);
        }
        float p0 = at.x * lrelu(hi0.x + hj0.x + c0.x)
                 + at.y * lrelu(hi0.y + hj0.y + c0.y)
                 + at.z * lrelu(hi0.z + hj0.z + c0.z)
                 + at.w * lrelu(hi0.w + hj0.w + c0.w);
        float p1 = at.x * lrelu(hi1.x + hj1.x + c1.x)
                 + at.y * lrelu(hi1.y + hj1.y + c1.y)
                 + at.z * lrelu(hi1.z + hj1.z + c1.z)
                 + at.w * lrelu(hi1.w + hj1.w + c1.w);
#pragma unroll
        for (int o = 16; o; o >>= 1) {
            p0 += __shfl_xor_sync(FULLM, p0, o);
            p1 += __shfl_xor_sync(FULLM, p1, o);
        }
        if (lane == 0) {
            g_score1[pos] = p0;
            if (ok1) g_score1[pos + 1] = p1;
        }
    }
}

// ---------------- fused layer-1 softmax/aggregate + gemm23 ----------------
__global__ void __launch_bounds__(256, 4) agg1_gemm_kernel(const float* __restrict__ bias1,
                                 const float* __restrict__ Wl2, const float* __restrict__ bl2,
                                 const float* __restrict__ Wl3, const float* __restrict__ bl3, int N) {
    __shared__ float sW[128 * 34];   // k<32: Wl3[d][k], k==32: Wl2[d]
    __shared__ float4 sB1[32];
    int tid = threadIdx.x;
    for (int i = tid; i < 128 * 33; i += blockDim.x) {
        int d = i / 33, k = i % 33;
        sW[d * 34 + k] = (k < 32) ? Wl3[d * 32 + k] : Wl2[d];
    }
    if (tid < 32) sB1[tid] = reinterpret_cast<const float4*>(bias1)[tid];
    __syncthreads();
    int lane = tid & 31;
    int wid = (blockIdx.x * blockDim.x + tid) >> 5;
    int nw = (gridDim.x * blockDim.x) >> 5;
    float b2 = __ldg(bl2);
    float b3 = __ldg(bl3 + lane);
    for (int i = wid; i < N; i += nw) {
        int beg = g_rowptr[i], end = g_rowptr[i + 1];
        int deg = end - beg;
        int p0 = beg + lane, p1 = beg + 32 + lane;
        bool a0 = p0 < end, a1 = p1 < end;
        float s0 = a0 ? g_score1[p0] : -INFINITY;
        float s1 = a1 ? g_score1[p1] : -INFINITY;
        int i0 = a0 ? g_srcs[p0] : 0;
        int i1 = a1 ? g_srcs[p1] : 0;
        float m = fmaxf(s0, s1);
        for (int p = beg + 64 + lane; p < end; p += 32) m = fmaxf(m, g_score1[p]);
#pragma unroll
        for (int o = 16; o; o >>= 1) m = fmaxf(m, __shfl_xor_sync(FULLM, m, o));
        float e0 = a0 ? expf(s0 - m) : 0.f;
        float e1 = a1 ? expf(s1 - m) : 0.f;
        float den = e0 + e1;
        for (int p = beg + 64 + lane; p < end; p += 32) den += expf(g_score1[p] - m);
#pragma unroll
        for (int o = 16; o; o >>= 1) den += __shfl_xor_sync(FULLM, den, o);
        float inv = 1.0f / (den + 1e-16f);
        float4 acc = make_float4(0.f, 0.f, 0.f, 0.f);
        int dmain = deg < 64 ? deg : 64;
        int k = 0;
        for (; k + 8 <= dmain; k += 8) {
            int   ss[8]; float ww[8];
#pragma unroll
            for (int j = 0; j < 8; j++) {
                ss[j] = __shfl_sync(FULLM, (k + j < 32) ? i0 : i1, (k + j) & 31);
                ww[j] = __shfl_sync(FULLM, (k + j < 32) ? e0 : e1, (k + j) & 31);
            }
            float4 vv[8];
#pragma unroll
            for (int j = 0; j < 8; j++)
                vv[j] = reinterpret_cast<const float4*>(g_h1 + (size_t)ss[j] * 128)[lane];
#pragma unroll
            for (int j = 0; j < 8; j++) {
                float aw = ww[j] * inv;
                acc.x = fmaf(aw, vv[j].x, acc.x);
                acc.y = fmaf(aw, vv[j].y, acc.y);
                acc.z = fmaf(aw, vv[j].z, acc.z);
                acc.w = fmaf(aw, vv[j].w, acc.w);
            }
        }
        for (; k + 4 <= dmain; k += 4) {
            int   ss[4]; float ww[4];
#pragma unroll
            for (int j = 0; j < 4; j++) {
                ss[j] = __shfl_sync(FULLM, (k + j < 32) ? i0 : i1, (k + j) & 31);
                ww[j] = __shfl_sync(FULLM, (k + j < 32) ? e0 : e1, (k + j) & 31);
            }
            float4 vv[4];
#pragma unroll
            for (int j = 0; j < 4; j++)
                vv[j] = reinterpret_cast<const float4*>(g_h1 + (size_t)ss[j] * 128)[lane];
#pragma unroll
            for (int j = 0; j < 4; j++) {
                float aw = ww[j] * inv;
                acc.x = fmaf(aw, vv[j].x, acc.x);
                acc.y = fmaf(aw, vv[j].y, acc.y);
                acc.z = fmaf(aw, vv[j].z, acc.z);
                acc.w = fmaf(aw, vv[j].w, acc.w);
            }
        }
        for (; k < dmain; k++) {
            int src  = __shfl_sync(FULLM, (k < 32) ? i0 : i1, k & 31);
            float ee = __shfl_sync(FULLM, (k < 32) ? e0 : e1, k & 31);
            float aw = ee * inv;
            float4 v = reinterpret_cast<const float4*>(g_h1 + (size_t)src * 128)[lane];
            acc.x = fmaf(aw, v.x, acc.x);
            acc.y = fmaf(aw, v.y, acc.y);
            acc.z = fmaf(aw, v.z, acc.z);
            acc.w = fmaf(aw, v.w, acc.w);
        }
        for (int p = beg + 64; p < end; p++) {
            float aw = expf(g_score1[p] - m) * inv;
            float4 v = reinterpret_cast<const float4*>(g_h1 + (size_t)g_srcs[p] * 128)[lane];
            acc.x = fmaf(aw, v.x, acc.x);
            acc.y = fmaf(aw, v.y, acc.y);
            acc.z = fmaf(aw, v.z, acc.z);
            acc.w = fmaf(aw, v.w, acc.w);
        }
        float4 bb = sB1[lane];
        float4 lr = make_float4(acc.x + bb.x, acc.y + bb.y, acc.z + bb.z, acc.w + bb.w);
        float acc3 = 0.f, acc2 = 0.f;
#pragma unroll
        for (int d = 0; d < 128; d++) {
            int r = d & 3;
            float comp = (r == 0) ? lr.x : (r == 1) ? lr.y : (r == 2) ? lr.z : lr.w;
            float v = __shfl_sync(FULLM, comp, d >> 2);
            acc3 = fmaf(v, sW[d * 34 + lane], acc3);
            acc2 = fmaf(v, sW[d * 34 + 32], acc2);
        }
        g_h3[(size_t)i * 32 + lane] = acc3 + b3;
        if (lane == 0) g_h2[i] = acc2 + b2;
    }
}

// ---------------- fused layer-2+3 edge scores: 2 edges per warp-iter ----------------
__global__ void __launch_bounds__(256, 4) score23_kernel(const float* __restrict__ ea,
                               const float* __restrict__ We2, const float* __restrict__ att2,
                               const float* __restrict__ We3, const float* __restrict__ att3, int E) {
    __shared__ float sW3[16 * 32];
    __shared__ float sW2[16];
    __shared__ float sA3[32];
    int tid = threadIdx.x;
    for (int i = tid; i < 16 * 32; i += blockDim.x) sW3[i] = We3[i];
    if (tid < 16) sW2[tid] = We2[tid];
    if (tid < 32) sA3[tid] = att3[tid];
    __syncthreads();
    int lane = tid & 31;
    int wid = (blockIdx.x * blockDim.x + tid) >> 5;
    int NW = (gridDim.x * blockDim.x) >> 5;
    float a2 = __ldg(att2);
    float at3 = sA3[lane];
    for (int pos = wid * 2; pos < E; pos += NW * 2) {
        bool ok1 = (pos + 1 < E);
        int pb = ok1 ? pos + 1 : pos;
        int4 E0 = g_edge[pos];
        int4 E1 = g_edge[pb];
        int s0 = E0.x, d0 = E0.y, e0 = E0.z;
        int s1 = E1.x, d1 = E1.y, e1 = E1.z;
        float h2j0 = __ldg(&g_h2[s0]), h2i0 = __ldg(&g_h2[d0]);
        float h2j1 = __ldg(&g_h2[s1]), h2i1 = __ldg(&g_h2[d1]);
        float h3j0 = g_h3[(size_t)s0 * 32 + lane];
        float h3i0 = g_h3[(size_t)d0 * 32 + lane];
        float h3j1 = g_h3[(size_t)s1 * 32 + lane];
        float h3i1 = g_h3[(size_t)d1 * 32 + lane];
        const float4* eaA = reinterpret_cast<const float4*>(ea + (size_t)e0 * 16);
        const float4* eaB = reinterpret_cast<const float4*>(ea + (size_t)e1 * 16);
        float ev0[16], ev1[16];
#pragma unroll
        for (int j = 0; j < 4; j++) {
            float4 t0 = __ldg(eaA + j);
            float4 t1 = __ldg(eaB + j);
            ev0[4*j+0]=t0.x; ev0[4*j+1]=t0.y; ev0[4*j+2]=t0.z; ev0[4*j+3]=t0.w;
            ev1[4*j+0]=t1.x; ev1[4*j+1]=t1.y; ev1[4*j+2]=t1.z; ev1[4*j+3]=t1.w;
        }
        float e30 = 0.f, e20 = 0.f, e31 = 0.f, e21 = 0.f;
#pragma unroll
        for (int d = 0; d < 16; d++) {
            float w3 = sW3[d * 32 + lane];
            float w2 = sW2[d];
            e30 = fmaf(ev0[d], w3, e30);
            e31 = fmaf(ev1[d], w3, e31);
            e20 = fmaf(ev0[d], w2, e20);
            e21 = fmaf(ev1[d], w2, e21);
        }
        float p30 = at3 * lrelu(h3i0 + h3j0 + e30);
        float p31 = at3 * lrelu(h3i1 + h3j1 + e31);
#pragma unroll
        for (int o = 16; o; o >>= 1) {
            p30 += __shfl_xor_sync(FULLM, p30, o);
            p31 += __shfl_xor_sync(FULLM, p31, o);
        }
        float q0 = a2 * lrelu(h2i0 + h2j0 + e20);
        float q1 = a2 * lrelu(h2i1 + h2j1 + e21);
        if (lane == 0) {
            g_s2a[pos] = q0;
            g_s3a[pos] = p30;
            if (ok1) { g_s2a[pos + 1] = q1; g_s3a[pos + 1] = p31; }
        }
    }
}

// ---------------- fused layer-2+3 softmax/aggregate + node gumbel sampling ----------------
__global__ void agg23_kernel(const float* __restrict__ bias2, const float* __restrict__ bias3, int N) {
    __shared__ unsigned long long sPk[8];
    __shared__ unsigned sLo[8];
    int tid = threadIdx.x;
    int lane = tid & 31;
    int warp = tid >> 5;
    int wid = (blockIdx.x * blockDim.x + tid) >> 5;
    int nw = (gridDim.x * blockDim.x) >> 5;
    float b2 = __ldg(bias2);
    float b3 = __ldg(bias3 + lane);
    unsigned gk0 = g_key1[0], gk1 = g_key1[1];
    unsigned long long bestPk = 0ull;
    unsigned bestLo = 0u;
    for (int i = wid; i < N; i += nw) {
        int beg = g_rowptr[i], end = g_rowptr[i + 1];
        int deg = end - beg;
        int p0 = beg + lane, p1 = beg + 32 + lane;
        bool a0 = p0 < end, a1 = p1 < end;
        float s20 = a0 ? g_s2a[p0] : -INFINITY;
        float s30 = a0 ? g_s3a[p0] : -INFINITY;
        float s21 = a1 ? g_s2a[p1] : -INFINITY;
        float s31 = a1 ? g_s3a[p1] : -INFINITY;
        int i0 = a0 ? g_srcs[p0] : 0;
        int i1 = a1 ? g_srcs[p1] : 0;
        float m2 = fmaxf(s20, s21), m3 = fmaxf(s30, s31);
        for (int p = beg + 64 + lane; p < end; p += 32) {
            m2 = fmaxf(m2, g_s2a[p]);
            m3 = fmaxf(m3, g_s3a[p]);
        }
#pragma unroll
        for (int o = 16; o; o >>= 1) {
            m2 = fmaxf(m2, __shfl_xor_sync(FULLM, m2, o));
            m3 = fmaxf(m3, __shfl_xor_sync(FULLM, m3, o));
        }
        float e20 = a0 ? expf(s20 - m2) : 0.f;
        float e21 = a1 ? expf(s21 - m2) : 0.f;
        float e30 = a0 ? expf(s30 - m3) : 0.f;
        float e31 = a1 ? expf(s31 - m3) : 0.f;
        float den2 = e20 + e21;
        float den3 = e30 + e31;
        float num2 = e20 * (a0 ? __ldg(&g_h2[i0]) : 0.f)
                   + e21 * (a1 ? __ldg(&g_h2[i1]) : 0.f);
        for (int p = beg + 64 + lane; p < end; p += 32) {
            float e2 = expf(g_s2a[p] - m2);
            den2 += e2;
            num2 += e2 * __ldg(&g_h2[g_srcs[p]]);
            den3 += expf(g_s3a[p] - m3);
        }
#pragma unroll
        for (int o = 16; o; o >>= 1) {
            den2 += __shfl_xor_sync(FULLM, den2, o);
            num2 += __shfl_xor_sync(FULLM, num2, o);
            den3 += __shfl_xor_sync(FULLM, den3, o);
        }
        float inv3 = 1.0f / (den3 + 1e-16f);
        float acc = 0.f;
        int dmain = deg < 64 ? deg : 64;
        int k = 0;
        for (; k + 8 <= dmain; k += 8) {
            int ss[8]; float ww[8];
#pragma unroll
            for (int j = 0; j < 8; j++) {
                ss[j] = __shfl_sync(FULLM, (k + j < 32) ? i0 : i1, (k + j) & 31);
                ww[j] = __shfl_sync(FULLM, (k + j < 32) ? e30 : e31, (k + j) & 31);
            }
            float vv[8];
#pragma unroll
            for (int j = 0; j < 8; j++)
                vv[j] = g_h3[(size_t)ss[j] * 32 + lane];
#pragma unroll
            for (int j = 0; j < 8; j++)
                acc = fmaf(ww[j] * inv3, vv[j], acc);
        }
        for (; k + 4 <= dmain; k += 4) {
            int ss[4]; float ww[4];
#pragma unroll
            for (int j = 0; j < 4; j++) {
                ss[j] = __shfl_sync(FULLM, (k + j < 32) ? i0 : i1, (k + j) & 31);
                ww[j] = __shfl_sync(FULLM, (k + j < 32) ? e30 : e31, (k + j) & 31);
            }
            float vv[4];
#pragma unroll
            for (int j = 0; j < 4; j++)
                vv[j] = g_h3[(size_t)ss[j] * 32 + lane];
#pragma unroll
            for (int j = 0; j < 4; j++)
                acc = fmaf(ww[j] * inv3, vv[j], acc);
        }
        for (; k < dmain; k++) {
            int src  = __shfl_sync(FULLM, (k < 32) ? i0 : i1, k & 31);
            float ee = __shfl_sync(FULLM, (k < 32) ? e30 : e31, k & 31);
            acc = fmaf(ee * inv3, g_h3[(size_t)src * 32 + lane], acc);
        }
        for (int p = beg + 64; p < end; p++) {
            float aw = expf(g_s3a[p] - m3) * inv3;
            acc = fmaf(aw, g_h3[(size_t)g_srcs[p] * 32 + lane], acc);
        }
        g_out3[(size_t)i * 32 + lane] = acc + b3;
        if (lane == 0) {
            float lg = num2 / (den2 + 1e-16f) + b2;
            g_out2[i] = lg;
            unsigned bits = jax_bits32(gk0, gk1, (unsigned)i);
            float z = lg + gumbel_bits(bits);
            unsigned long long pk = ((unsigned long long)ordf(z) << 32)
                                  | (unsigned long long)(0xFFFFFFFFu - (unsigned)i);
            if (pk > bestPk) bestPk = pk;
            unsigned lo = ordf(lg);
            if (lo > bestLo) bestLo = lo;
        }
    }
    if (lane == 0) { sPk[warp] = bestPk; sLo[warp] = bestLo; }
    __syncthreads();
    if (tid == 0) {
        unsigned long long bp = sPk[0];
        unsigned bl = sLo[0];
#pragma unroll
        for (int j = 1; j < 8; j++) {
            if (sPk[j] > bp) bp = sPk[j];
            if (sLo[j] > bl) bl = sLo[j];
        }
        atomicMax(&g_packed, bp);
        atomicMax(&g_lmax_ord, bl);
    }
}

// ---------------- finalize: sumexp + node_lp + action sampling ----------------
__global__ void finalize_kernel(float* __restrict__ out, int N) {
    __shared__ float ssum[32];
    int tid = threadIdx.x;
    int lane = tid & 31;
    int warp = tid >> 5;
    float lmax = ordinv(g_lmax_ord);
    float s = 0.f;
    for (int i = tid; i < N; i += 1024) s += expf(g_out2[i] - lmax);
#pragma unroll
    for (int o = 16; o; o >>= 1) s += __shfl_xor_sync(FULLM, s, o);
    if (lane == 0) ssum[warp] = s;
    __syncthreads();
    if (tid < 32) {
        float v = ssum[tid];
#pragma unroll
        for (int o = 16; o; o >>= 1) v += __shfl_xor_sync(FULLM, v, o);
        if (tid == 0) ssum[0] = v;
    }
    __syncthreads();
    float S = ssum[0];
    if (tid < 32) {
        unsigned long long pk = g_packed;
        unsigned sel = 0xFFFFFFFFu - (unsigned)(pk & 0xFFFFFFFFull);
        float node_lp = g_out2[sel] - lmax - logf(S);

        float logit = g_out3[(size_t)sel * 32 + lane];
        unsigned bits = jax_bits32(g_key2[0], g_key2[1], (unsigned)lane);
        float z = logit + gumbel_bits(bits);

        float bz = z;
        int bi = lane;
#pragma unroll
        for (int o = 16; o; o >>= 1) {
            float oz = __shfl_xor_sync(FULLM, bz, o);
            int oi = __shfl_xor_sync(FULLM, bi, o);
            if (oz > bz || (oz == bz && oi < bi)) { bz = oz; bi = oi; }
        }
        float m = logit;
#pragma unroll
        for (int o = 16; o; o >>= 1) m = fmaxf(m, __shfl_xor_sync(FULLM, m, o));
        float se = expf(logit - m);
#pragma unroll
        for (int o = 16; o; o >>= 1) se += __shfl_xor_sync(FULLM, se, o);
        float sel_logit = __shfl_sync(FULLM, logit, bi);
        float action_lp = sel_logit - m - logf(se);
        if (lane == 0) {
            out[0] = (float)sel;
            out[1] = (float)bi;
            out[2] = node_lp + action_lp;
        }
    }
}

// ---------------- launch ----------------
extern "C" void kernel_launch(void* const* d_in, const int* in_sizes, int n_in,
                              void* d_out, int out_size) {
    const float* x     = (const float*)d_in[0];
    const int*   ei    = (const int*)d_in[1];
    const float* ea    = (const float*)d_in[2];
    const float* Wl1   = (const float*)d_in[3];
    const float* bl1   = (const float*)d_in[4];
    const float* We1   = (const float*)d_in[5];
    const float* att1  = (const float*)d_in[6];
    const float* bias1 = (const float*)d_in[7];
    const float* Wl2   = (const float*)d_in[8];
    const float* bl2   = (const float*)d_in[9];
    const float* We2   = (const float*)d_in[10];
    const float* att2  = (const float*)d_in[11];
    const float* bias2 = (const float*)d_in[12];
    const float* Wl3   = (const float*)d_in[13];
    const float* bl3   = (const float*)d_in[14];
    const float* We3   = (const float*)d_in[15];
    const float* att3  = (const float*)d_in[16];
    const float* bias3 = (const float*)d_in[17];

    int N = in_sizes[0] / 128;
    int E = in_sizes[1] / 2;
    float* out = (float*)d_out;

    const int smem1 = (16384 + 128 + 4096) * 4;
    cudaFuncSetAttribute(gemm1_kernel, cudaFuncAttributeMaxDynamicSharedMemorySize, smem1);

    int NB = (N + 255) / 256;

    // Fork: gemm1 (depends only on x, Wl1) overlaps the CSR build chain.
    cudaStream_t s2;
    cudaEvent_t evFork, evJoin;
    cudaStreamCreateWithFlags(&s2, cudaStreamNonBlocking);
    cudaEventCreateWithFlags(&evFork, cudaEventDisableTiming);
    cudaEventCreateWithFlags(&evJoin, cudaEventDisableTiming);

    cudaEventRecord(evFork, 0);
    cudaStreamWaitEvent(s2, evFork, 0);
    gemm1_kernel<<<296, 256, smem1, s2>>>(x, Wl1, bl1, N);
    cudaEventRecord(evJoin, s2);

    hist_kernel<<<(E + 255) / 256, 256>>>(ei, E);
    scanA_kernel<<<NB, 256>>>(N);
    scanB_kernel<<<1, 256>>>(NB, N);
    scanC_kernel<<<NB, 256>>>(N);
    scatter_kernel<<<(E + 255) / 256, 256>>>(ei, E);

    cudaStreamWaitEvent(0, evJoin, 0);

    score1_kernel<<<2368, 256>>>(ea, We1, att1, E);
    agg1_gemm_kernel<<<1184, 256>>>(bias1, Wl2, bl2, Wl3, bl3, N);

    score23_kernel<<<2368, 256>>>(ea, We2, att2, We3, att3, E);
    agg23_kernel<<<1184, 256>>>(bias2, bias3, N);

    finalize_kernel<<<1, 1024>>>(out, N);

    cudaStreamDestroy(s2);
    cudaEventDestroy(evFork);
    cudaEventDestroy(evJoin);
}